// round 11
// baseline (speedup 1.0000x reference)
#include <cuda_runtime.h>
#include <math.h>
#include <stdint.h>

#define N5 5000

// ---------------- scratch (device globals; no allocation allowed) ----------------
__device__ float g_win[100000032];        // [4][5000][5000] (+pad) = M^2, tf32-rounded
__device__ float g_colpart[4*40*5000];
__device__ float g_icol2[4*5000];
__device__ float g_h[5000*128];
__device__ float g_base[5000*128];
__device__ float g_P[4*5000*128];         // P_k [k][n], tf32-rounded, icol2 folded
__device__ float g_part[16*5000*128];     // split-K partials (16 chunks)
__device__ float g_des[5000*256];         // exact fp32 (output)
__device__ float g_desr[5000*256];        // tf32-rounded copy for logits MMA
__device__ float g_fc2r[256*5000];        // fc2_w elementwise tf32-rounded
__device__ float g_clkz[4*256];           // clk column per z
__device__ float g_mnp[200*128];
__device__ float g_mxp[200*128];

__device__ __forceinline__ float eluf(float v){ return v > 0.f ? v : expm1f(v); }

__device__ __forceinline__ unsigned tf32r(float f){
    unsigned u; asm("cvt.rna.tf32.f32 %0, %1;" : "=r"(u) : "f"(f)); return u;
}
__device__ __forceinline__ float tf32rf(float f){ return __uint_as_float(tf32r(f)); }
__device__ __forceinline__ void splitf(float v, unsigned& hi, unsigned& lo){
    unsigned h = tf32r(v);
    lo = tf32r(v - __uint_as_float(h));
    hi = h;
}
__device__ __forceinline__ unsigned uf(float f){ return __float_as_uint(f); }
__device__ __forceinline__ void mma8(float* c, const unsigned* a, unsigned b0, unsigned b1){
    asm volatile("mma.sync.aligned.m16n8k8.row.col.f32.tf32.tf32.f32 "
        "{%0,%1,%2,%3},{%4,%5,%6,%7},{%8,%9},{%0,%1,%2,%3};"
        : "+f"(c[0]),"+f"(c[1]),"+f"(c[2]),"+f"(c[3])
        : "r"(a[0]),"r"(a[1]),"r"(a[2]),"r"(a[3]),"r"(b0),"r"(b1));
}

// ---------------- clk column pack ----------------
__global__ void k_clkz(const float* __restrict__ clk)
{
    int e = threadIdx.x;
#pragma unroll
    for (int z = 0; z < 4; z++)
        g_clkz[z*256 + e] = clk[e*32 + (31 - 8*z)];
}

// ---------------- coalesced per-column min/max partials (input x only) ----------------
__global__ void k_mm_part(const float* __restrict__ xsrc, int C)
{
    const float* src = xsrc ? xsrc : g_base;
    __shared__ float smn[4][128], smx[4][128];
    const int t = threadIdx.x;
    const int c = t % C, rp = t / C;
    const int r0 = blockIdx.x*25;
    float mn = 3.4e38f, mx = -3.4e38f;
    for (int r = rp; r < 25; r += 4){
        float v = src[(size_t)(r0 + r)*C + c];
        mn = fminf(mn, v); mx = fmaxf(mx, v);
    }
    smn[rp][c] = mn; smx[rp][c] = mx;
    __syncthreads();
    if (rp == 0){
        mn = fminf(fminf(smn[0][c], smn[1][c]), fminf(smn[2][c], smn[3][c]));
        mx = fmaxf(fmaxf(smx[0][c], smx[1][c]), fmaxf(smx[2][c], smx[3][c]));
        g_mnp[blockIdx.x*128 + c] = mn;
        g_mxp[blockIdx.x*128 + c] = mx;
    }
}

// reduce 200 partials per column, then apply normalization -> g_h
__global__ void k_apply2(const float* __restrict__ xsrc, int C)
{
    const float* src = xsrc ? xsrc : g_base;
    __shared__ float smn[128], smx[128];
    for (int c = threadIdx.x; c < C; c += blockDim.x){
        float mn = 3.4e38f, mx = -3.4e38f;
#pragma unroll 8
        for (int b = 0; b < 200; b++){
            mn = fminf(mn, g_mnp[b*128 + c]);
            mx = fmaxf(mx, g_mxp[b*128 + c]);
        }
        smn[c] = mn; smx[c] = mx;
    }
    __syncthreads();
    int total = N5*C;
    for (int idx = blockIdx.x*blockDim.x + threadIdx.x; idx < total;
         idx += gridDim.x*blockDim.x){
        int c = idx % C;
        g_h[idx] = (src[idx] - smn[c]) / (smx[c] - smn[c]);
    }
}

// ---------------- build Win, SYMMETRIC (k-paired float2 smem) ----------------
__global__ __launch_bounds__(256,2) void k_build_sym(const float* __restrict__ A,
                                                     const float* __restrict__ V)
{
    __shared__ __align__(16) float2 smPair[4][8][132];   // Ahp, Alp, Bhp, Blp
    __shared__ float scol[4][128];
    __shared__ float msum[2][128];
    float2 (*Ahp)[132] = smPair[0];
    float2 (*Alp)[132] = smPair[1];
    float2 (*Bhp)[132] = smPair[2];
    float2 (*Blp)[132] = smPair[3];
    float (*tr)[132] = (float(*)[132])&smPair[0][0][0];  // 32x132 floats = Ahp+Alp

    const int z = blockIdx.y;
    int bi = 0, rem = blockIdx.x;
    while (rem >= 40 - bi){ rem -= 40 - bi; bi++; }
    const int bj = bi + rem;

    const int t = threadIdx.x;
    const int w = t >> 5, lane = t & 31, g = lane >> 2, ctg = lane & 3;
    const int wm = w >> 1, wn = w & 1;
    const int r = t & 127, seg = t >> 7;
    const int garow = min(bi*128 + r, N5-1);
    const int gbrow = min(bj*128 + r, N5-1);
    const float* vaRow = V + (size_t)garow*256;
    const float* vbRow = V + (size_t)gbrow*256;
    const float* ck = g_clkz + z*256;

    float4 Pva[2], Pvb[2], Pck[2];
#pragma unroll
    for (int j = 0; j < 2; j++){
        int col = seg*8 + j*4;
        Pva[j] = *(const float4*)&vaRow[col];
        Pvb[j] = *(const float4*)&vbRow[col];
        Pck[j] = *(const float4*)&ck[col];
    }

    float acc[2][8][4];
#pragma unroll
    for (int mt = 0; mt < 2; mt++)
#pragma unroll
        for (int nt = 0; nt < 8; nt++)
#pragma unroll
            for (int q = 0; q < 4; q++) acc[mt][nt][q] = 0.f;

    for (int c = 0; c < 16; c++){
        __syncthreads();
        {
            // pairs (k, k+4): x from Pva[0]/Pvb[0] (cols +0..3), y from [1] (+4..7)
            float a0[4] = {Pva[0].x*Pck[0].x, Pva[0].y*Pck[0].y, Pva[0].z*Pck[0].z, Pva[0].w*Pck[0].w};
            float a1[4] = {Pva[1].x*Pck[1].x, Pva[1].y*Pck[1].y, Pva[1].z*Pck[1].z, Pva[1].w*Pck[1].w};
            float b0[4] = {Pvb[0].x, Pvb[0].y, Pvb[0].z, Pvb[0].w};
            float b1[4] = {Pvb[1].x, Pvb[1].y, Pvb[1].z, Pvb[1].w};
#pragma unroll
            for (int q = 0; q < 4; q++){
                unsigned h0,l0,h1,l1;
                int kp = seg*4 + q;
                splitf(a0[q], h0, l0); splitf(a1[q], h1, l1);
                Ahp[kp][r] = make_float2(__uint_as_float(h0), __uint_as_float(h1));
                Alp[kp][r] = make_float2(__uint_as_float(l0), __uint_as_float(l1));
                splitf(b0[q], h0, l0); splitf(b1[q], h1, l1);
                Bhp[kp][r] = make_float2(__uint_as_float(h0), __uint_as_float(h1));
                Blp[kp][r] = make_float2(__uint_as_float(l0), __uint_as_float(l1));
            }
        }
        if (c+1 < 16){
            const int k0 = (c+1)*16;
#pragma unroll
            for (int j = 0; j < 2; j++){
                int col = k0 + seg*8 + j*4;
                Pva[j] = *(const float4*)&vaRow[col];
                Pvb[j] = *(const float4*)&vbRow[col];
                Pck[j] = *(const float4*)&ck[col];
            }
        }
        __syncthreads();
#pragma unroll
        for (int kk = 0; kk < 2; kk++){
            const int kp = kk*4 + ctg;
            unsigned ah[2][4], al[2][4];
#pragma unroll
            for (int mt = 0; mt < 2; mt++){
                int m0 = wm*32 + mt*16;
                float2 h0 = Ahp[kp][m0+g], h8 = Ahp[kp][m0+g+8];
                float2 l0 = Alp[kp][m0+g], l8 = Alp[kp][m0+g+8];
                ah[mt][0]=uf(h0.x); ah[mt][1]=uf(h8.x); ah[mt][2]=uf(h0.y); ah[mt][3]=uf(h8.y);
                al[mt][0]=uf(l0.x); al[mt][1]=uf(l8.x); al[mt][2]=uf(l0.y); al[mt][3]=uf(l8.y);
            }
#pragma unroll
            for (int nt = 0; nt < 8; nt++){
                int n = wn*64 + nt*8 + g;
                float2 bhp = Bhp[kp][n];
                float2 blp = Blp[kp][n];
                unsigned bh0 = uf(bhp.x), bh1 = uf(bhp.y);
                unsigned bl0 = uf(blp.x), bl1 = uf(blp.y);
#pragma unroll
                for (int mt = 0; mt < 2; mt++){
                    mma8(acc[mt][nt], ah[mt], bh0, bh1);
                    mma8(acc[mt][nt], ah[mt], bl0, bl1);
                    mma8(acc[mt][nt], al[mt], bh0, bh1);
                }
            }
        }
    }

    const size_t zbase = (size_t)z*25000000;

    // normal tile: store tf32-rounded X; colpart from exact X
#pragma unroll
    for (int nt = 0; nt < 8; nt++){
        int jb = bj*128 + wn*64 + nt*8 + ctg*2;
        float aj0 = (jb   < N5) ? A[jb]   : 0.f;
        float aj1 = (jb+1 < N5) ? A[jb+1] : 0.f;
        float se = 0.f, so = 0.f;
#pragma unroll
        for (int mt = 0; mt < 2; mt++){
            int i0 = bi*128 + wm*32 + mt*16 + g;
            float m00 = acc[mt][nt][0]*aj0; float X00 = m00*m00; X00 *= X00;
            float m01 = acc[mt][nt][1]*aj1; float X01 = m01*m01; X01 *= X01;
            float m10 = acc[mt][nt][2]*aj0; float X10 = m10*m10; X10 *= X10;
            float m11 = acc[mt][nt][3]*aj1; float X11 = m11*m11; X11 *= X11;
            bool ok0 = i0 < N5, ok1 = (i0+8) < N5;
            if (ok0 && jb < N5){
                if (jb+1 < N5) *(float2*)&g_win[zbase + (size_t)i0*N5 + jb] =
                                   make_float2(tf32rf(X00), tf32rf(X01));
                else g_win[zbase + (size_t)i0*N5 + jb] = tf32rf(X00);
            }
            if (ok1 && jb < N5){
                if (jb+1 < N5) *(float2*)&g_win[zbase + (size_t)(i0+8)*N5 + jb] =
                                   make_float2(tf32rf(X10), tf32rf(X11));
                else g_win[zbase + (size_t)(i0+8)*N5 + jb] = tf32rf(X10);
            }
            se += (ok0?X00:0.f) + (ok1?X10:0.f);
            so += (ok0?X01:0.f) + (ok1?X11:0.f);
        }
#pragma unroll
        for (int off = 4; off < 32; off <<= 1){
            se += __shfl_xor_sync(0xffffffffu, se, off);
            so += __shfl_xor_sync(0xffffffffu, so, off);
        }
        if (lane < 4){
            scol[wm][wn*64 + nt*8 + lane*2]     = se;
            scol[wm][wn*64 + nt*8 + lane*2 + 1] = so;
        }
    }
    __syncthreads();
    if (t < 128){
        float s = scol[0][t] + scol[1][t] + scol[2][t] + scol[3][t];
        int j = bj*128 + t;
        if (j < N5) g_colpart[((size_t)z*40 + bi)*N5 + j] = s;
    }

    if (bi == bj) return;

    // mirror tile
    float ai[2][2];
#pragma unroll
    for (int mt = 0; mt < 2; mt++){
        int i0 = bi*128 + wm*32 + mt*16 + g;
        ai[mt][0] = A[i0];
        ai[mt][1] = A[i0+8];
    }

    float rs[2][2] = {{0.f,0.f},{0.f,0.f}};
#pragma unroll
    for (int nt = 0; nt < 8; nt++){
        int jb = bj*128 + wn*64 + nt*8 + ctg*2;
        bool j0ok = jb < N5, j1ok = (jb+1) < N5;
#pragma unroll
        for (int mt = 0; mt < 2; mt++){
            float m00 = acc[mt][nt][0]*ai[mt][0]; float X00 = m00*m00; X00 *= X00;
            float m01 = acc[mt][nt][1]*ai[mt][0]; float X01 = m01*m01; X01 *= X01;
            float m10 = acc[mt][nt][2]*ai[mt][1]; float X10 = m10*m10; X10 *= X10;
            float m11 = acc[mt][nt][3]*ai[mt][1]; float X11 = m11*m11; X11 *= X11;
            rs[mt][0] += (j0ok?X00:0.f) + (j1ok?X01:0.f);
            rs[mt][1] += (j0ok?X10:0.f) + (j1ok?X11:0.f);
        }
    }
#pragma unroll
    for (int off = 1; off < 4; off <<= 1){
#pragma unroll
        for (int mt = 0; mt < 2; mt++){
            rs[mt][0] += __shfl_xor_sync(0xffffffffu, rs[mt][0], off);
            rs[mt][1] += __shfl_xor_sync(0xffffffffu, rs[mt][1], off);
        }
    }
    if (ctg == 0){
#pragma unroll
        for (int mt = 0; mt < 2; mt++){
            if (wn == 0){
                msum[0][wm*32 + mt*16 + g]     = rs[mt][0];
                msum[0][wm*32 + mt*16 + g + 8] = rs[mt][1];
            } else {
                msum[1][wm*32 + mt*16 + g]     = rs[mt][0];
                msum[1][wm*32 + mt*16 + g + 8] = rs[mt][1];
            }
        }
    }
    __syncthreads();
    if (t < 128)
        g_colpart[((size_t)z*40 + bj)*N5 + bi*128 + t] = msum[0][t] + msum[1][t];

    // staged transpose write of mirror tile, 4 chunks of 32 j-rows
    for (int c = 0; c < 4; c++){
        __syncthreads();
        if (wn == (c >> 1)){
#pragma unroll
            for (int q = 0; q < 4; q++){
                int nt = (c & 1)*4 + q;
                int jl = nt*8 + ctg*2 - (c & 1)*32;
#pragma unroll
                for (int mt = 0; mt < 2; mt++){
                    int il = wm*32 + mt*16 + g;
                    float m00 = acc[mt][nt][0]*ai[mt][0]; float X00 = m00*m00; X00 *= X00;
                    float m01 = acc[mt][nt][1]*ai[mt][0]; float X01 = m01*m01; X01 *= X01;
                    float m10 = acc[mt][nt][2]*ai[mt][1]; float X10 = m10*m10; X10 *= X10;
                    float m11 = acc[mt][nt][3]*ai[mt][1]; float X11 = m11*m11; X11 *= X11;
                    tr[jl  ][il]   = tf32rf(X00);
                    tr[jl  ][il+8] = tf32rf(X10);
                    tr[jl+1][il]   = tf32rf(X01);
                    tr[jl+1][il+8] = tf32rf(X11);
                }
            }
        }
        __syncthreads();
        int jg0 = bj*128 + c*32;
        for (int idx = t; idx < 32*32; idx += 256){
            int row = idx >> 5, c4 = (idx & 31)*4;
            int jg = jg0 + row;
            if (jg < N5)
                *(float4*)&g_win[zbase + (size_t)jg*N5 + bi*128 + c4] =
                    *(float4*)&tr[row][c4];
        }
    }
}

__global__ void k_colreduce()
{
    int z = blockIdx.y;
    int j = blockIdx.x*blockDim.x + threadIdx.x;
    if (j < N5){
        float s = 0.f;
        for (int b = 0; b < 40; b++) s += g_colpart[((size_t)z*40 + b)*N5 + j];
        float c = fmaxf(sqrtf(s), 1e-12f);
        g_icol2[z*N5 + j] = 1.0f/(c*c);
    }
}

// ---------------- tensor-core proj: base = h@W[0]; P_k = tf32r((h@W[k+1])*icol2) --------
template<int CI, int CO>
__global__ __launch_bounds__(256,2) void k_proj_tc(const float* __restrict__ W)
{
    constexpr int NT = CO/16;
    __shared__ unsigned Hh[128][17], Hl[128][17];
    __shared__ unsigned Ws[16][CO+4];

    const int j = blockIdx.y;
    const float* Wj = W + (size_t)j*CI*CO;
    const int r0 = blockIdx.x*128;
    const int t = threadIdx.x;
    const int w = t >> 5, lane = t & 31, g = lane >> 2, ctg = lane & 3;
    const int wm = w >> 1, wn = w & 1;

    float acc[2][NT][4];
#pragma unroll
    for (int mt = 0; mt < 2; mt++)
#pragma unroll
        for (int nt = 0; nt < NT; nt++)
#pragma unroll
            for (int q = 0; q < 4; q++) acc[mt][nt][q] = 0.f;

    for (int c0 = 0; c0 < CI; c0 += 16){
        __syncthreads();
#pragma unroll
        for (int i = 0; i < 2; i++){
            int idx = t + i*256;
            int m = idx >> 2, k4 = (idx & 3)*4;
            int gr = min(r0 + m, N5-1);
            float4 v = *(const float4*)&g_h[(size_t)gr*CI + c0 + k4];
            unsigned h0,l0;
            splitf(v.x,h0,l0); Hh[m][k4+0]=h0; Hl[m][k4+0]=l0;
            splitf(v.y,h0,l0); Hh[m][k4+1]=h0; Hl[m][k4+1]=l0;
            splitf(v.z,h0,l0); Hh[m][k4+2]=h0; Hl[m][k4+2]=l0;
            splitf(v.w,h0,l0); Hh[m][k4+3]=h0; Hl[m][k4+3]=l0;
        }
        for (int idx = t; idx < 16*CO; idx += 256){
            int kk2 = idx / CO, o = idx % CO;
            Ws[kk2][o] = tf32r(Wj[(size_t)(c0+kk2)*CO + o]);
        }
        __syncthreads();
#pragma unroll
        for (int kk = 0; kk < 2; kk++){
            const int k = kk*8;
            unsigned ah[2][4], al[2][4];
#pragma unroll
            for (int mt = 0; mt < 2; mt++){
                int m0 = wm*32 + mt*16;
                ah[mt][0]=Hh[m0+g][k+ctg];   ah[mt][1]=Hh[m0+g+8][k+ctg];
                ah[mt][2]=Hh[m0+g][k+ctg+4]; ah[mt][3]=Hh[m0+g+8][k+ctg+4];
                al[mt][0]=Hl[m0+g][k+ctg];   al[mt][1]=Hl[m0+g+8][k+ctg];
                al[mt][2]=Hl[m0+g][k+ctg+4]; al[mt][3]=Hl[m0+g+8][k+ctg+4];
            }
#pragma unroll
            for (int nt = 0; nt < NT; nt++){
                int n = wn*(CO/2) + nt*8 + g;
                unsigned b0 = Ws[k+ctg][n], b1 = Ws[k+ctg+4][n];
#pragma unroll
                for (int mt = 0; mt < 2; mt++){
                    mma8(acc[mt][nt], ah[mt], b0, b1);
                    mma8(acc[mt][nt], al[mt], b0, b1);
                }
            }
        }
    }

#pragma unroll
    for (int mt = 0; mt < 2; mt++){
        int i0 = r0 + wm*32 + mt*16 + g;
        if (j == 0){
#pragma unroll
            for (int nt = 0; nt < NT; nt++){
                int n = wn*(CO/2) + nt*8 + ctg*2;
                if (i0 < N5)
                    *(float2*)&g_base[(size_t)i0*CO + n] =
                        make_float2(acc[mt][nt][0], acc[mt][nt][1]);
                if (i0+8 < N5)
                    *(float2*)&g_base[(size_t)(i0+8)*CO + n] =
                        make_float2(acc[mt][nt][2], acc[mt][nt][3]);
            }
        } else {
            float s0 = (i0   < N5) ? g_icol2[(j-1)*N5 + i0]   : 0.f;
            float s8 = (i0+8 < N5) ? g_icol2[(j-1)*N5 + i0+8] : 0.f;
            float* P = g_P + (size_t)(j-1)*N5*CO;
#pragma unroll
            for (int nt = 0; nt < NT; nt++){
                int n = wn*(CO/2) + nt*8 + ctg*2;
                if (i0 < N5)
                    *(float2*)&P[(size_t)i0*CO + n] =
                        make_float2(tf32rf(acc[mt][nt][0]*s0), tf32rf(acc[mt][nt][1]*s0));
                if (i0+8 < N5)
                    *(float2*)&P[(size_t)(i0+8)*CO + n] =
                        make_float2(tf32rf(acc[mt][nt][2]*s8), tf32rf(acc[mt][nt][3]*s8));
            }
        }
    }
}

// ---------------- SIMT proj for des (bias + elu); exact + rounded copies ----------
template<int CI, int CO>
__global__ __launch_bounds__(256) void k_proj_des(const float* __restrict__ W,
                                                  const float* __restrict__ bias)
{
    constexpr int PER = (64*CO)/256;
    const int r0 = blockIdx.x*64;
    const int t = threadIdx.x;

    __shared__ float ht[64][33];
    __shared__ float Wt[32][CO+1];

    float acc[PER];
#pragma unroll
    for (int p = 0; p < PER; p++) acc[p] = 0.f;

    for (int c0 = 0; c0 < CI; c0 += 32){
        for (int idx = t; idx < 64*32; idx += 256){
            int r = idx >> 5, cc = idx & 31;
            int gr = r0 + r;
            ht[r][cc] = (gr < N5) ? g_h[(size_t)gr*CI + c0 + cc] : 0.f;
        }
        for (int idx = t; idx < 32*CO; idx += 256){
            int cc = idx / CO, o = idx % CO;
            Wt[cc][o] = W[(size_t)(c0+cc)*CO + o];
        }
        __syncthreads();
#pragma unroll
        for (int p = 0; p < PER; p++){
            int oi = t + p*256;
            int rr = oi / CO, o = oi % CO;
            float s = acc[p];
#pragma unroll
            for (int cc = 0; cc < 32; cc++) s += ht[rr][cc]*Wt[cc][o];
            acc[p] = s;
        }
        __syncthreads();
    }
#pragma unroll
    for (int p = 0; p < PER; p++){
        int oi = t + p*256;
        int rr = oi / CO, o = oi % CO;
        int gr = r0 + rr;
        if (gr < N5){
            float v = eluf(acc[p] + bias[o]);
            g_des[(size_t)gr*CO + o] = v;
            g_desr[(size_t)gr*CO + o] = tf32rf(v);
        }
    }
}

// ---------------- winapply: k-paired float2 smem, double-buffered, split-K 16 ----------
template<int BN>
__global__ __launch_bounds__(256,2) void k_winapply_tc()
{
    constexpr int NT = BN/16;
    constexpr int NB4 = BN/4;
    constexpr int TP = 16*NB4;                 // B pair tasks
    constexpr int NB2 = (TP + 255)/256;
    constexpr int PS = 132;                    // float2 row stride
    constexpr int ASZ = 16*PS;                 // float2 per A stage
    constexpr int BSZ = 16*PS;
    extern __shared__ __align__(16) float2 smP[];   // A[2][ASZ], B[2][BSZ]
    float2* Apt = smP;
    float2* Bpt = smP + 2*ASZ;

    const int t = threadIdx.x;
    const int w = t >> 5, lane = t & 31, g = lane >> 2, ctg = lane & 3;
    const int wm = w >> 1, wn = w & 1;
    const int bi = blockIdx.x, y = blockIdx.y;
    const int slab = y >> 2;
    const int part = y & 3;
    const int kbase = part*1248;
    const int kend  = (part == 3) ? N5 : kbase + 1248;
    const int nch   = (part == 3) ? 40 : 39;
    const float* __restrict__ Wk = g_win + (size_t)slab*25000000;
    const float* __restrict__ Pk = g_P + (size_t)slab*N5*BN;
    const int ar = t & 127, aseg = t >> 7;
    const float* aptr = Wk + (size_t)min(bi*128 + ar, N5-1)*N5;

    float4 aR[4], bLo[NB2], bHi[NB2];

    auto loadRegs = [&](int c){
        const int k0 = kbase + c*32;
#pragma unroll
        for (int j = 0; j < 4; j++) aR[j] = *(const float4*)&aptr[k0 + aseg*16 + j*4];
#pragma unroll
        for (int i = 0; i < NB2; i++){
            int idx = t + i*256;
            if (idx < TP){
                int kp = idx / NB4, bc = idx % NB4;
                int kl = (kp >> 2)*8 + (kp & 3);
                int gl = k0 + kl, gh = gl + 4;
                bLo[i] = (gl < kend) ? *(const float4*)&Pk[(size_t)gl*BN + bc*4]
                                     : make_float4(0,0,0,0);
                bHi[i] = (gh < kend) ? *(const float4*)&Pk[(size_t)gh*BN + bc*4]
                                     : make_float4(0,0,0,0);
            }
        }
    };
    auto storeTiles = [&](int s){
        float2* As = Apt + s*ASZ;
        float2* Bs = Bpt + s*BSZ;
#pragma unroll
        for (int jj = 0; jj < 2; jj++){
            int kk = aseg*2 + jj;
            float4 lo = aR[2*jj], hi = aR[2*jj+1];
            float2* ab = As + (kk*4)*PS + ar;
            ab[0*PS] = make_float2(lo.x, hi.x);
            ab[1*PS] = make_float2(lo.y, hi.y);
            ab[2*PS] = make_float2(lo.z, hi.z);
            ab[3*PS] = make_float2(lo.w, hi.w);
        }
#pragma unroll
        for (int i = 0; i < NB2; i++){
            int idx = t + i*256;
            if (idx < TP){
                int kp = idx / NB4, bc = idx % NB4;
                float2* bb = Bs + kp*PS + bc*4;
                *(float4*)&bb[0] = make_float4(bLo[i].x, bHi[i].x, bLo[i].y, bHi[i].y);
                *(float4*)&bb[2] = make_float4(bLo[i].z, bHi[i].z, bLo[i].w, bHi[i].w);
            }
        }
    };

    float acc[2][NT][4];
#pragma unroll
    for (int mt = 0; mt < 2; mt++)
#pragma unroll
        for (int nt = 0; nt < NT; nt++)
#pragma unroll
            for (int q = 0; q < 4; q++) acc[mt][nt][q] = 0.f;

    loadRegs(0);
    storeTiles(0);
    if (nch > 1) loadRegs(1);
    __syncthreads();

    for (int c = 0; c < nch; c++){
        const int s = c & 1;
        if (c+1 < nch) storeTiles(s^1);
        if (c+2 < nch) loadRegs(c+2);
        const float2* As = Apt + s*ASZ;
        const float2* Bs = Bpt + s*BSZ;
#pragma unroll
        for (int kk = 0; kk < 4; kk++){
            const int kp = kk*4 + ctg;
            unsigned a[2][4];
#pragma unroll
            for (int mt = 0; mt < 2; mt++){
                int m0 = wm*32 + mt*16;
                float2 p0 = As[kp*PS + m0+g];
                float2 p8 = As[kp*PS + m0+g+8];
                a[mt][0]=uf(p0.x); a[mt][1]=uf(p8.x); a[mt][2]=uf(p0.y); a[mt][3]=uf(p8.y);
            }
#pragma unroll
            for (int nt = 0; nt < NT; nt++){
                int n = wn*(BN/2) + nt*8 + g;
                float2 bp = Bs[kp*PS + n];
                unsigned b0 = uf(bp.x), b1 = uf(bp.y);
                mma8(acc[0][nt], a[0], b0, b1);
                mma8(acc[1][nt], a[1], b0, b1);
            }
        }
        __syncthreads();
    }

    float* dst = g_part + (size_t)y*N5*BN;
#pragma unroll
    for (int mt = 0; mt < 2; mt++){
#pragma unroll
        for (int nt = 0; nt < NT; nt++){
            int i0 = bi*128 + wm*32 + mt*16 + g;
            int n  = wn*(BN/2) + nt*8 + ctg*2;
            if (i0 < N5)
                *(float2*)&dst[(size_t)i0*BN + n] =
                    make_float2(acc[mt][nt][0], acc[mt][nt][1]);
            if (i0+8 < N5)
                *(float2*)&dst[(size_t)(i0+8)*BN + n] =
                    make_float2(acc[mt][nt][2], acc[mt][nt][3]);
        }
    }
}

// ---------------- fused: reduce 16 partials + elu -> g_base, col min/max partials ------
template<int C>
__global__ void k_winred_mm()
{
    __shared__ float smn[4][128], smx[4][128];
    const int t = threadIdx.x;
    const int c = t % C, rp = t / C;
    const int r0 = blockIdx.x*25;
    float mn = 3.4e38f, mx = -3.4e38f;
    for (int r = rp; r < 25; r += 4){
        size_t idx = (size_t)(r0 + r)*C + c;
        float v = g_base[idx];
#pragma unroll
        for (int s = 0; s < 16; s++) v += g_part[(size_t)s*N5*C + idx];
        v = eluf(v);
        g_base[idx] = v;
        mn = fminf(mn, v); mx = fmaxf(mx, v);
    }
    smn[rp][c] = mn; smx[rp][c] = mx;
    __syncthreads();
    if (rp == 0){
        mn = fminf(fminf(smn[0][c], smn[1][c]), fminf(smn[2][c], smn[3][c]));
        mx = fmaxf(fmaxf(smx[0][c], smx[1][c]), fmaxf(smx[2][c], smx[3][c]));
        g_mnp[blockIdx.x*128 + c] = mn;
        g_mxp[blockIdx.x*128 + c] = mx;
    }
}

// ---------------- fc2_w elementwise tf32 round ----------------
__global__ void k_fc2r(const float* __restrict__ B)
{
    int idx = blockIdx.x*blockDim.x + threadIdx.x;
    if (idx < 256*N5) g_fc2r[idx] = tf32rf(B[idx]);
}

// ---------------- logits = des @ fc2_w + fc2_b ----------------
__global__ __launch_bounds__(256,2) void k_linear_tc(const float* __restrict__ bias,
                                                     float* __restrict__ out)
{
    __shared__ unsigned As[32][136];
    __shared__ __align__(16) unsigned Bs[32][136];

    const int t = threadIdx.x;
    const int w = t >> 5, lane = t & 31, g = lane >> 2, ctg = lane & 3;
    const int wm = w >> 1, wn = w & 1;
    const int bi = blockIdx.y, bj = blockIdx.x;
    const int ar = t >> 1, aseg = t & 1;
    const float* aptr = g_desr + (size_t)min(bi*128 + ar, N5-1)*256;

    float acc[2][8][4];
#pragma unroll
    for (int mt = 0; mt < 2; mt++)
#pragma unroll
        for (int nt = 0; nt < 8; nt++)
#pragma unroll
            for (int q = 0; q < 4; q++) acc[mt][nt][q] = 0.f;

    for (int c = 0; c < 8; c++){
        const int k0 = c*32;
        __syncthreads();
#pragma unroll
        for (int j = 0; j < 4; j++){
            int col = aseg*16 + j*4;
            float4 v = *(const float4*)&aptr[k0 + col];
            As[col+0][ar] = uf(v.x);
            As[col+1][ar] = uf(v.y);
            As[col+2][ar] = uf(v.z);
            As[col+3][ar] = uf(v.w);
        }
#pragma unroll
        for (int i = 0; i < 4; i++){
            int idx = t + i*256;
            int br = idx >> 5, bc = idx & 31;
            int gj = bj*128 + bc*4;
            float4 v;
            if (gj + 3 < N5) v = *(const float4*)&g_fc2r[(size_t)(k0+br)*N5 + gj];
            else {
                v = make_float4(0,0,0,0);
                if (gj+0 < N5) v.x = g_fc2r[(size_t)(k0+br)*N5 + gj+0];
                if (gj+1 < N5) v.y = g_fc2r[(size_t)(k0+br)*N5 + gj+1];
                if (gj+2 < N5) v.z = g_fc2r[(size_t)(k0+br)*N5 + gj+2];
                if (gj+3 < N5) v.w = g_fc2r[(size_t)(k0+br)*N5 + gj+3];
            }
            *(uint4*)&Bs[br][bc*4] = *(uint4*)&v;
        }
        __syncthreads();
#pragma unroll
        for (int kk = 0; kk < 4; kk++){
            const int k = kk*8;
            unsigned a[2][4];
#pragma unroll
            for (int mt = 0; mt < 2; mt++){
                int m0 = wm*32 + mt*16;
                a[mt][0]=As[k+ctg][m0+g];   a[mt][1]=As[k+ctg][m0+g+8];
                a[mt][2]=As[k+ctg+4][m0+g]; a[mt][3]=As[k+ctg+4][m0+g+8];
            }
#pragma unroll
            for (int nt = 0; nt < 8; nt++){
                int n = wn*64 + nt*8 + g;
                unsigned b0 = Bs[k+ctg][n], b1 = Bs[k+ctg+4][n];
                mma8(acc[0][nt], a[0], b0, b1);
                mma8(acc[1][nt], a[1], b0, b1);
            }
        }
    }
#pragma unroll
    for (int mt = 0; mt < 2; mt++){
#pragma unroll
        for (int nt = 0; nt < 8; nt++){
            int i0 = bi*128 + wm*32 + mt*16 + g;
            int jb = bj*128 + wn*64 + nt*8 + ctg*2;
            float b0 = (jb   < N5) ? bias[jb]   : 0.f;
            float b1 = (jb+1 < N5) ? bias[jb+1] : 0.f;
            if (i0 < N5 && jb < N5){
                if (jb+1 < N5)
                    *(float2*)&out[(size_t)i0*N5 + jb] =
                        make_float2(acc[mt][nt][0]+b0, acc[mt][nt][1]+b1);
                else out[(size_t)i0*N5 + jb] = acc[mt][nt][0]+b0;
            }
            if (i0+8 < N5 && jb < N5){
                if (jb+1 < N5)
                    *(float2*)&out[(size_t)(i0+8)*N5 + jb] =
                        make_float2(acc[mt][nt][2]+b0, acc[mt][nt][3]+b1);
                else out[(size_t)(i0+8)*N5 + jb] = acc[mt][nt][2]+b0;
            }
        }
    }
}

// ---------------- log-softmax, register-resident ----------------
__global__ void k_logsoftmax(float* __restrict__ out)
{
    const int row = blockIdx.x;
    float* p = out + (size_t)row*N5;
    const int t = threadIdx.x;
    float4 v[5];
    bool have[5];
    float mx = -3.4e38f;
#pragma unroll
    for (int s = 0; s < 5; s++){
        int i4 = t + s*256;
        have[s] = i4 < 1250;
        if (have[s]){
            v[s] = *(const float4*)&p[i4*4];
            mx = fmaxf(mx, fmaxf(fmaxf(v[s].x, v[s].y), fmaxf(v[s].z, v[s].w)));
        }
    }
    __shared__ float sh[256];
    sh[t] = mx; __syncthreads();
    for (int s = 128; s > 0; s >>= 1){
        if (t < s) sh[t] = fmaxf(sh[t], sh[t+s]);
        __syncthreads();
    }
    mx = sh[0]; __syncthreads();
    float sum = 0.f;
#pragma unroll
    for (int s = 0; s < 5; s++)
        if (have[s])
            sum += expf(v[s].x-mx) + expf(v[s].y-mx) + expf(v[s].z-mx) + expf(v[s].w-mx);
    sh[t] = sum; __syncthreads();
    for (int s = 128; s > 0; s >>= 1){
        if (t < s) sh[t] += sh[t+s];
        __syncthreads();
    }
    float lse = mx + logf(sh[0]);
#pragma unroll
    for (int s = 0; s < 5; s++){
        if (have[s]){
            int i4 = t + s*256;
            *(float4*)&p[i4*4] = make_float4(v[s].x-lse, v[s].y-lse, v[s].z-lse, v[s].w-lse);
        }
    }
}

__global__ void k_copydes(float* __restrict__ out)
{
    int total = N5*256;
    for (int idx = blockIdx.x*blockDim.x + threadIdx.x; idx < total;
         idx += gridDim.x*blockDim.x)
        out[idx] = g_des[idx];
}

// ---------------- launcher ----------------
extern "C" void kernel_launch(void* const* d_in, const int* in_sizes, int n_in,
                              void* d_out, int out_size)
{
    (void)in_sizes; (void)n_in;
    const float* x    = (const float*)d_in[0];
    const float* V    = (const float*)d_in[1];
    const float* A    = (const float*)d_in[2];
    const float* clk  = (const float*)d_in[3];
    const float* Wc[6] = {(const float*)d_in[4], (const float*)d_in[5],
                          (const float*)d_in[6], (const float*)d_in[7],
                          (const float*)d_in[8], (const float*)d_in[9]};
    const float* fc1w = (const float*)d_in[10];
    const float* fc1b = (const float*)d_in[11];
    const float* fc2w = (const float*)d_in[12];
    const float* fc2b = (const float*)d_in[13];
    float* out = (float*)d_out;

    const int smWin = (2*16*132 + 2*16*132)*8;     // 67584 B
    cudaFuncSetAttribute(k_winapply_tc<96>,  cudaFuncAttributeMaxDynamicSharedMemorySize, smWin);
    cudaFuncSetAttribute(k_winapply_tc<128>, cudaFuncAttributeMaxDynamicSharedMemorySize, smWin);

    // preamble
    k_clkz<<<1,256>>>(clk);
    k_mm_part<<<200,512>>>(x, 128);
    k_apply2<<<640,256>>>(x, 128);

    // Build Win (tf32-rounded M^2, symmetric tiles) + column norms -> icol2
    k_build_sym<<<dim3(820,4),256>>>(A, V);
    k_colreduce<<<dim3(20,4),256>>>();

    // Layer 1: 128 -> 96
    k_proj_tc<128,96><<<dim3(40,5),256>>>(Wc[0]);
    k_winapply_tc<96><<<dim3(40,16),256,smWin>>>();
    k_winred_mm<96><<<200,384>>>();
    k_apply2<<<480,256>>>(nullptr, 96);

    // Layers 2-5: 96 -> 96
    for (int L = 1; L < 5; L++){
        k_proj_tc<96,96><<<dim3(40,5),256>>>(Wc[L]);
        k_winapply_tc<96><<<dim3(40,16),256,smWin>>>();
        k_winred_mm<96><<<200,384>>>();
        k_apply2<<<480,256>>>(nullptr, 96);
    }

    // Layer 6: 96 -> 128
    k_proj_tc<96,128><<<dim3(40,5),256>>>(Wc[5]);
    k_winapply_tc<128><<<dim3(40,16),256,smWin>>>();
    k_winred_mm<128><<<200,512>>>();
    k_apply2<<<640,256>>>(nullptr, 128);

    // des = elu(h @ fc1_w + fc1_b)  (exact + rounded copies)
    k_proj_des<128,256><<<79,256>>>(fc1w, fc1b);

    // logits + log_softmax
    k_fc2r<<<5000,256>>>(fc2w);
    k_linear_tc<<<dim3(40,40),256>>>(fc2b, out);
    k_logsoftmax<<<5000,256>>>(out);

    // second output: des
    if (out_size >= 25000000 + N5*256)
        k_copydes<<<640,256>>>(out + 25000000);
}

// round 14
// speedup vs baseline: 1.2180x; 1.2180x over previous
#include <cuda_runtime.h>
#include <math.h>
#include <stdint.h>

#define N5 5000

// ---------------- scratch (device globals; no allocation allowed) ----------------
__device__ float g_win[100000032];        // [4][5000][5000] (+pad) = M^2, tf32-rounded
__device__ float g_colpart[4*40*5000];
__device__ float g_icol2[4*5000];
__device__ float g_base[5000*128];        // layer activations (post-elu), proj INPUT only
__device__ float g_acc[5000*128];         // base term h@W0 (proj j==0 output)
__device__ float g_P[4*5000*128];         // P_k [k][n], tf32-rounded, icol2 folded
__device__ float g_part[16*5000*128];     // split-K partials (16 chunks)
__device__ float g_des[5000*256];         // exact fp32 (output)
__device__ float g_desr[5000*256];        // tf32-rounded copy for logits MMA
__device__ float g_fc2r[256*5000];        // fc2_w elementwise tf32-rounded
__device__ float g_clkz[4*256];           // clk column per z
__device__ float g_mnp[200*128];
__device__ float g_mxp[200*128];
__device__ float g_nmn[128];
__device__ float g_nd[128];

__device__ __forceinline__ float eluf(float v){ return v > 0.f ? v : expm1f(v); }

__device__ __forceinline__ unsigned tf32r(float f){
    unsigned u; asm("cvt.rna.tf32.f32 %0, %1;" : "=r"(u) : "f"(f)); return u;
}
__device__ __forceinline__ float tf32rf(float f){ return __uint_as_float(tf32r(f)); }
__device__ __forceinline__ void splitf(float v, unsigned& hi, unsigned& lo){
    unsigned h = tf32r(v);
    lo = tf32r(v - __uint_as_float(h));
    hi = h;
}
__device__ __forceinline__ unsigned uf(float f){ return __float_as_uint(f); }
__device__ __forceinline__ void mma8(float* c, const unsigned* a, unsigned b0, unsigned b1){
    asm volatile("mma.sync.aligned.m16n8k8.row.col.f32.tf32.tf32.f32 "
        "{%0,%1,%2,%3},{%4,%5,%6,%7},{%8,%9},{%0,%1,%2,%3};"
        : "+f"(c[0]),"+f"(c[1]),"+f"(c[2]),"+f"(c[3])
        : "r"(a[0]),"r"(a[1]),"r"(a[2]),"r"(a[3]),"r"(b0),"r"(b1));
}

// ---------------- clk column pack ----------------
__global__ void k_clkz(const float* __restrict__ clk)
{
    int e = threadIdx.x;
#pragma unroll
    for (int z = 0; z < 4; z++)
        g_clkz[z*256 + e] = clk[e*32 + (31 - 8*z)];
}

// ---------------- coalesced per-column min/max partials (input x only) ----------------
__global__ void k_mm_part(const float* __restrict__ src, int C)
{
    __shared__ float smn[4][128], smx[4][128];
    const int t = threadIdx.x;
    const int c = t % C, rp = t / C;
    const int r0 = blockIdx.x*25;
    float mn = 3.4e38f, mx = -3.4e38f;
    for (int r = rp; r < 25; r += 4){
        float v = src[(size_t)(r0 + r)*C + c];
        mn = fminf(mn, v); mx = fmaxf(mx, v);
    }
    smn[rp][c] = mn; smx[rp][c] = mx;
    __syncthreads();
    if (rp == 0){
        mn = fminf(fminf(smn[0][c], smn[1][c]), fminf(smn[2][c], smn[3][c]));
        mx = fmaxf(fmaxf(smx[0][c], smx[1][c]), fmaxf(smx[2][c], smx[3][c]));
        g_mnp[blockIdx.x*128 + c] = mn;
        g_mxp[blockIdx.x*128 + c] = mx;
    }
}

// finalize per-column norm constants (same b-ascending order as before)
__global__ void k_colfin(int C)
{
    int c = threadIdx.x;
    if (c < C){
        float mn = 3.4e38f, mx = -3.4e38f;
        for (int b = 0; b < 200; b++){
            mn = fminf(mn, g_mnp[b*128 + c]);
            mx = fmaxf(mx, g_mxp[b*128 + c]);
        }
        g_nmn[c] = mn;
        g_nd[c]  = mx - mn;
    }
}

// ---------------- build Win, SYMMETRIC (inline split + reg prefetch; R10-proven) --------
__global__ __launch_bounds__(256,2) void k_build_sym(const float* __restrict__ A,
                                                     const float* __restrict__ V)
{
    __shared__ unsigned smemAB[4][16][136];
    __shared__ float scol[4][128];
    __shared__ float msum[2][128];
    unsigned (*Ah)[136] = smemAB[0];
    unsigned (*Al)[136] = smemAB[1];
    unsigned (*Bh)[136] = smemAB[2];
    unsigned (*Bl)[136] = smemAB[3];
    float (*tr)[132] = (float(*)[132])(&smemAB[0][0][0]);  // 32x132 fits in Ah+Al

    const int z = blockIdx.y;
    int bi = 0, rem = blockIdx.x;
    while (rem >= 40 - bi){ rem -= 40 - bi; bi++; }
    const int bj = bi + rem;

    const int t = threadIdx.x;
    const int w = t >> 5, lane = t & 31, g = lane >> 2, ctg = lane & 3;
    const int wm = w >> 1, wn = w & 1;
    const int r = t >> 1, seg = t & 1;
    const int garow = min(bi*128 + r, N5-1);
    const int gbrow = min(bj*128 + r, N5-1);
    const float* vaRow = V + (size_t)garow*256;
    const float* vbRow = V + (size_t)gbrow*256;
    const float* ck = g_clkz + z*256;

    float4 Pva[2], Pvb[2], Pck[2];
#pragma unroll
    for (int j = 0; j < 2; j++){
        int col = seg*8 + j*4;
        Pva[j] = *(const float4*)&vaRow[col];
        Pvb[j] = *(const float4*)&vbRow[col];
        Pck[j] = *(const float4*)&ck[col];
    }

    float acc[2][8][4];
#pragma unroll
    for (int mt = 0; mt < 2; mt++)
#pragma unroll
        for (int nt = 0; nt < 8; nt++)
#pragma unroll
            for (int q = 0; q < 4; q++) acc[mt][nt][q] = 0.f;

    for (int c = 0; c < 16; c++){
        __syncthreads();
#pragma unroll
        for (int j = 0; j < 2; j++){
            int col = seg*8 + j*4;
            unsigned h, l;
            splitf(Pva[j].x*Pck[j].x, h, l); Ah[col+0][r]=h; Al[col+0][r]=l;
            splitf(Pva[j].y*Pck[j].y, h, l); Ah[col+1][r]=h; Al[col+1][r]=l;
            splitf(Pva[j].z*Pck[j].z, h, l); Ah[col+2][r]=h; Al[col+2][r]=l;
            splitf(Pva[j].w*Pck[j].w, h, l); Ah[col+3][r]=h; Al[col+3][r]=l;
            splitf(Pvb[j].x, h, l); Bh[col+0][r]=h; Bl[col+0][r]=l;
            splitf(Pvb[j].y, h, l); Bh[col+1][r]=h; Bl[col+1][r]=l;
            splitf(Pvb[j].z, h, l); Bh[col+2][r]=h; Bl[col+2][r]=l;
            splitf(Pvb[j].w, h, l); Bh[col+3][r]=h; Bl[col+3][r]=l;
        }
        if (c+1 < 16){
            const int k0 = (c+1)*16;
#pragma unroll
            for (int j = 0; j < 2; j++){
                int col = k0 + seg*8 + j*4;
                Pva[j] = *(const float4*)&vaRow[col];
                Pvb[j] = *(const float4*)&vbRow[col];
                Pck[j] = *(const float4*)&ck[col];
            }
        }
        __syncthreads();
#pragma unroll
        for (int kk = 0; kk < 2; kk++){
            const int k = kk*8;
            unsigned ah[2][4], al[2][4];
#pragma unroll
            for (int mt = 0; mt < 2; mt++){
                int m0 = wm*32 + mt*16;
                ah[mt][0]=Ah[k+ctg][m0+g];   ah[mt][1]=Ah[k+ctg][m0+g+8];
                ah[mt][2]=Ah[k+ctg+4][m0+g]; ah[mt][3]=Ah[k+ctg+4][m0+g+8];
                al[mt][0]=Al[k+ctg][m0+g];   al[mt][1]=Al[k+ctg][m0+g+8];
                al[mt][2]=Al[k+ctg+4][m0+g]; al[mt][3]=Al[k+ctg+4][m0+g+8];
            }
#pragma unroll
            for (int nt = 0; nt < 8; nt++){
                int n = wn*64 + nt*8 + g;
                unsigned bh0 = Bh[k+ctg][n], bh1 = Bh[k+ctg+4][n];
                unsigned bl0 = Bl[k+ctg][n], bl1 = Bl[k+ctg+4][n];
#pragma unroll
                for (int mt = 0; mt < 2; mt++){
                    mma8(acc[mt][nt], ah[mt], bh0, bh1);
                    mma8(acc[mt][nt], ah[mt], bl0, bl1);
                    mma8(acc[mt][nt], al[mt], bh0, bh1);
                }
            }
        }
    }

    const size_t zbase = (size_t)z*25000000;

    // normal tile: store tf32-rounded X; colpart from exact X
#pragma unroll
    for (int nt = 0; nt < 8; nt++){
        int jb = bj*128 + wn*64 + nt*8 + ctg*2;
        float aj0 = (jb   < N5) ? A[jb]   : 0.f;
        float aj1 = (jb+1 < N5) ? A[jb+1] : 0.f;
        float se = 0.f, so = 0.f;
#pragma unroll
        for (int mt = 0; mt < 2; mt++){
            int i0 = bi*128 + wm*32 + mt*16 + g;
            float m00 = acc[mt][nt][0]*aj0; float X00 = m00*m00; X00 *= X00;
            float m01 = acc[mt][nt][1]*aj1; float X01 = m01*m01; X01 *= X01;
            float m10 = acc[mt][nt][2]*aj0; float X10 = m10*m10; X10 *= X10;
            float m11 = acc[mt][nt][3]*aj1; float X11 = m11*m11; X11 *= X11;
            bool ok0 = i0 < N5, ok1 = (i0+8) < N5;
            if (ok0 && jb < N5){
                if (jb+1 < N5) *(float2*)&g_win[zbase + (size_t)i0*N5 + jb] =
                                   make_float2(tf32rf(X00), tf32rf(X01));
                else g_win[zbase + (size_t)i0*N5 + jb] = tf32rf(X00);
            }
            if (ok1 && jb < N5){
                if (jb+1 < N5) *(float2*)&g_win[zbase + (size_t)(i0+8)*N5 + jb] =
                                   make_float2(tf32rf(X10), tf32rf(X11));
                else g_win[zbase + (size_t)(i0+8)*N5 + jb] = tf32rf(X10);
            }
            se += (ok0?X00:0.f) + (ok1?X10:0.f);
            so += (ok0?X01:0.f) + (ok1?X11:0.f);
        }
#pragma unroll
        for (int off = 4; off < 32; off <<= 1){
            se += __shfl_xor_sync(0xffffffffu, se, off);
            so += __shfl_xor_sync(0xffffffffu, so, off);
        }
        if (lane < 4){
            scol[wm][wn*64 + nt*8 + lane*2]     = se;
            scol[wm][wn*64 + nt*8 + lane*2 + 1] = so;
        }
    }
    __syncthreads();
    if (t < 128){
        float s = scol[0][t] + scol[1][t] + scol[2][t] + scol[3][t];
        int j = bj*128 + t;
        if (j < N5) g_colpart[((size_t)z*40 + bi)*N5 + j] = s;
    }

    if (bi == bj) return;

    // mirror tile
    float ai[2][2];
#pragma unroll
    for (int mt = 0; mt < 2; mt++){
        int i0 = bi*128 + wm*32 + mt*16 + g;
        ai[mt][0] = A[i0];
        ai[mt][1] = A[i0+8];
    }

    float rs[2][2] = {{0.f,0.f},{0.f,0.f}};
#pragma unroll
    for (int nt = 0; nt < 8; nt++){
        int jb = bj*128 + wn*64 + nt*8 + ctg*2;
        bool j0ok = jb < N5, j1ok = (jb+1) < N5;
#pragma unroll
        for (int mt = 0; mt < 2; mt++){
            float m00 = acc[mt][nt][0]*ai[mt][0]; float X00 = m00*m00; X00 *= X00;
            float m01 = acc[mt][nt][1]*ai[mt][0]; float X01 = m01*m01; X01 *= X01;
            float m10 = acc[mt][nt][2]*ai[mt][1]; float X10 = m10*m10; X10 *= X10;
            float m11 = acc[mt][nt][3]*ai[mt][1]; float X11 = m11*m11; X11 *= X11;
            rs[mt][0] += (j0ok?X00:0.f) + (j1ok?X01:0.f);
            rs[mt][1] += (j0ok?X10:0.f) + (j1ok?X11:0.f);
        }
    }
#pragma unroll
    for (int off = 1; off < 4; off <<= 1){
#pragma unroll
        for (int mt = 0; mt < 2; mt++){
            rs[mt][0] += __shfl_xor_sync(0xffffffffu, rs[mt][0], off);
            rs[mt][1] += __shfl_xor_sync(0xffffffffu, rs[mt][1], off);
        }
    }
    if (ctg == 0){
#pragma unroll
        for (int mt = 0; mt < 2; mt++){
            if (wn == 0){
                msum[0][wm*32 + mt*16 + g]     = rs[mt][0];
                msum[0][wm*32 + mt*16 + g + 8] = rs[mt][1];
            } else {
                msum[1][wm*32 + mt*16 + g]     = rs[mt][0];
                msum[1][wm*32 + mt*16 + g + 8] = rs[mt][1];
            }
        }
    }
    __syncthreads();
    if (t < 128)
        g_colpart[((size_t)z*40 + bj)*N5 + bi*128 + t] = msum[0][t] + msum[1][t];

    // staged transpose write of mirror tile, 4 chunks of 32 j-rows
    for (int c = 0; c < 4; c++){
        __syncthreads();
        if (wn == (c >> 1)){
#pragma unroll
            for (int q = 0; q < 4; q++){
                int nt = (c & 1)*4 + q;
                int jl = nt*8 + ctg*2 - (c & 1)*32;
#pragma unroll
                for (int mt = 0; mt < 2; mt++){
                    int il = wm*32 + mt*16 + g;
                    float m00 = acc[mt][nt][0]*ai[mt][0]; float X00 = m00*m00; X00 *= X00;
                    float m01 = acc[mt][nt][1]*ai[mt][0]; float X01 = m01*m01; X01 *= X01;
                    float m10 = acc[mt][nt][2]*ai[mt][1]; float X10 = m10*m10; X10 *= X10;
                    float m11 = acc[mt][nt][3]*ai[mt][1]; float X11 = m11*m11; X11 *= X11;
                    tr[jl  ][il]   = tf32rf(X00);
                    tr[jl  ][il+8] = tf32rf(X10);
                    tr[jl+1][il]   = tf32rf(X01);
                    tr[jl+1][il+8] = tf32rf(X11);
                }
            }
        }
        __syncthreads();
        int jg0 = bj*128 + c*32;
        for (int idx = t; idx < 32*32; idx += 256){
            int row = idx >> 5, c4 = (idx & 31)*4;
            int jg = jg0 + row;
            if (jg < N5)
                *(float4*)&g_win[zbase + (size_t)jg*N5 + bi*128 + c4] =
                    *(float4*)&tr[row][c4];
        }
    }
}

__global__ void k_colreduce()
{
    int z = blockIdx.y;
    int j = blockIdx.x*blockDim.x + threadIdx.x;
    if (j < N5){
        float s = 0.f;
        for (int b = 0; b < 40; b++) s += g_colpart[((size_t)z*40 + b)*N5 + j];
        float c = fmaxf(sqrtf(s), 1e-12f);
        g_icol2[z*N5 + j] = 1.0f/(c*c);
    }
}

// ---------------- tensor-core proj, inline fmaxmin via g_nmn/g_nd ----------------
// reads src (x or g_base), writes g_acc (j==0) / g_P (j>0). No aliasing.
template<int CI, int CO>
__global__ __launch_bounds__(256,2) void k_proj_tc(const float* __restrict__ W,
                                                   const float* __restrict__ xsrc)
{
    constexpr int NT = CO/16;
    __shared__ unsigned Hh[128][17], Hl[128][17];
    __shared__ unsigned Ws[16][CO+4];
    __shared__ float nmn[CI], nd[CI];

    const float* src = xsrc ? xsrc : g_base;
    const int j = blockIdx.y;
    const float* Wj = W + (size_t)j*CI*CO;
    const int r0 = blockIdx.x*128;
    const int t = threadIdx.x;
    const int w = t >> 5, lane = t & 31, g = lane >> 2, ctg = lane & 3;
    const int wm = w >> 1, wn = w & 1;

    for (int c = t; c < CI; c += 256){
        nmn[c] = g_nmn[c];
        nd[c]  = g_nd[c];
    }

    float acc[2][NT][4];
#pragma unroll
    for (int mt = 0; mt < 2; mt++)
#pragma unroll
        for (int nt = 0; nt < NT; nt++)
#pragma unroll
            for (int q = 0; q < 4; q++) acc[mt][nt][q] = 0.f;

    for (int c0 = 0; c0 < CI; c0 += 16){
        __syncthreads();
#pragma unroll
        for (int i = 0; i < 2; i++){
            int idx = t + i*256;
            int m = idx >> 2, k4 = (idx & 3)*4;
            int gr = min(r0 + m, N5-1);
            float4 v = *(const float4*)&src[(size_t)gr*CI + c0 + k4];
            v.x = (v.x - nmn[c0+k4+0]) / nd[c0+k4+0];
            v.y = (v.y - nmn[c0+k4+1]) / nd[c0+k4+1];
            v.z = (v.z - nmn[c0+k4+2]) / nd[c0+k4+2];
            v.w = (v.w - nmn[c0+k4+3]) / nd[c0+k4+3];
            unsigned h0,l0;
            splitf(v.x,h0,l0); Hh[m][k4+0]=h0; Hl[m][k4+0]=l0;
            splitf(v.y,h0,l0); Hh[m][k4+1]=h0; Hl[m][k4+1]=l0;
            splitf(v.z,h0,l0); Hh[m][k4+2]=h0; Hl[m][k4+2]=l0;
            splitf(v.w,h0,l0); Hh[m][k4+3]=h0; Hl[m][k4+3]=l0;
        }
        for (int idx = t; idx < 16*CO; idx += 256){
            int kk2 = idx / CO, o = idx % CO;
            Ws[kk2][o] = tf32r(Wj[(size_t)(c0+kk2)*CO + o]);
        }
        __syncthreads();
#pragma unroll
        for (int kk = 0; kk < 2; kk++){
            const int k = kk*8;
            unsigned ah[2][4], al[2][4];
#pragma unroll
            for (int mt = 0; mt < 2; mt++){
                int m0 = wm*32 + mt*16;
                ah[mt][0]=Hh[m0+g][k+ctg];   ah[mt][1]=Hh[m0+g+8][k+ctg];
                ah[mt][2]=Hh[m0+g][k+ctg+4]; ah[mt][3]=Hh[m0+g+8][k+ctg+4];
                al[mt][0]=Hl[m0+g][k+ctg];   al[mt][1]=Hl[m0+g+8][k+ctg];
                al[mt][2]=Hl[m0+g][k+ctg+4]; al[mt][3]=Hl[m0+g+8][k+ctg+4];
            }
#pragma unroll
            for (int nt = 0; nt < NT; nt++){
                int n = wn*(CO/2) + nt*8 + g;
                unsigned b0 = Ws[k+ctg][n], b1 = Ws[k+ctg+4][n];
#pragma unroll
                for (int mt = 0; mt < 2; mt++){
                    mma8(acc[mt][nt], ah[mt], b0, b1);
                    mma8(acc[mt][nt], al[mt], b0, b1);
                }
            }
        }
    }

#pragma unroll
    for (int mt = 0; mt < 2; mt++){
        int i0 = r0 + wm*32 + mt*16 + g;
        if (j == 0){
#pragma unroll
            for (int nt = 0; nt < NT; nt++){
                int n = wn*(CO/2) + nt*8 + ctg*2;
                if (i0 < N5)
                    *(float2*)&g_acc[(size_t)i0*CO + n] =
                        make_float2(acc[mt][nt][0], acc[mt][nt][1]);
                if (i0+8 < N5)
                    *(float2*)&g_acc[(size_t)(i0+8)*CO + n] =
                        make_float2(acc[mt][nt][2], acc[mt][nt][3]);
            }
        } else {
            float s0 = (i0   < N5) ? g_icol2[(j-1)*N5 + i0]   : 0.f;
            float s8 = (i0+8 < N5) ? g_icol2[(j-1)*N5 + i0+8] : 0.f;
            float* P = g_P + (size_t)(j-1)*N5*CO;
#pragma unroll
            for (int nt = 0; nt < NT; nt++){
                int n = wn*(CO/2) + nt*8 + ctg*2;
                if (i0 < N5)
                    *(float2*)&P[(size_t)i0*CO + n] =
                        make_float2(tf32rf(acc[mt][nt][0]*s0), tf32rf(acc[mt][nt][1]*s0));
                if (i0+8 < N5)
                    *(float2*)&P[(size_t)(i0+8)*CO + n] =
                        make_float2(tf32rf(acc[mt][nt][2]*s8), tf32rf(acc[mt][nt][3]*s8));
            }
        }
    }
}

// ---------------- SIMT proj for des (bias + elu), inline normalization ----------
template<int CI, int CO>
__global__ __launch_bounds__(256) void k_proj_des(const float* __restrict__ W,
                                                  const float* __restrict__ bias)
{
    constexpr int PER = (64*CO)/256;
    const int r0 = blockIdx.x*64;
    const int t = threadIdx.x;

    __shared__ float ht[64][33];
    __shared__ float Wt[32][CO+1];
    __shared__ float nmn[CI], nd[CI];

    for (int c = t; c < CI; c += 256){
        nmn[c] = g_nmn[c];
        nd[c]  = g_nd[c];
    }
    __syncthreads();

    float acc[PER];
#pragma unroll
    for (int p = 0; p < PER; p++) acc[p] = 0.f;

    for (int c0 = 0; c0 < CI; c0 += 32){
        for (int idx = t; idx < 64*32; idx += 256){
            int r = idx >> 5, cc = idx & 31;
            int gr = r0 + r;
            float v = 0.f;
            if (gr < N5)
                v = (g_base[(size_t)gr*CI + c0 + cc] - nmn[c0+cc]) / nd[c0+cc];
            ht[r][cc] = v;
        }
        for (int idx = t; idx < 32*CO; idx += 256){
            int cc = idx / CO, o = idx % CO;
            Wt[cc][o] = W[(size_t)(c0+cc)*CO + o];
        }
        __syncthreads();
#pragma unroll
        for (int p = 0; p < PER; p++){
            int oi = t + p*256;
            int rr = oi / CO, o = oi % CO;
            float s = acc[p];
#pragma unroll
            for (int cc = 0; cc < 32; cc++) s += ht[rr][cc]*Wt[cc][o];
            acc[p] = s;
        }
        __syncthreads();
    }
#pragma unroll
    for (int p = 0; p < PER; p++){
        int oi = t + p*256;
        int rr = oi / CO, o = oi % CO;
        int gr = r0 + rr;
        if (gr < N5){
            float v = eluf(acc[p] + bias[o]);
            g_des[(size_t)gr*CO + o] = v;
            g_desr[(size_t)gr*CO + o] = tf32rf(v);
        }
    }
}

// ---------------- winapply: double-buffered, split-K 16 (1248-aligned; R10-proven) ------
template<int BN>
__global__ __launch_bounds__(256,2) void k_winapply_tc()
{
    constexpr int BP = (BN==96) ? 104 : 136;
    constexpr int NT = BN/16;
    constexpr int NB4 = BN/4;
    constexpr int BCNT = (32*NB4)/256;
    constexpr int ASZ = 32*136;
    constexpr int BSZ = 32*BP;
    extern __shared__ __align__(16) unsigned smemU[];   // As[2][32][136], Bs[2][32][BP]
    unsigned* Asm = smemU;
    unsigned* Bsm = smemU + 2*ASZ;

    const int t = threadIdx.x;
    const int w = t >> 5, lane = t & 31, g = lane >> 2, ctg = lane & 3;
    const int wm = w >> 1, wn = w & 1;
    const int bi = blockIdx.x, y = blockIdx.y;
    const int slab = y >> 2;
    const int part = y & 3;
    const int kbase = part*1248;
    const int kend  = (part == 3) ? N5 : kbase + 1248;
    const int nch   = (part == 3) ? 40 : 39;
    const float* __restrict__ Wk = g_win + (size_t)slab*25000000;
    const float* __restrict__ Pk = g_P + (size_t)slab*N5*BN;
    const int ar = t >> 1, aseg = t & 1;
    const float* aptr = Wk + (size_t)min(bi*128 + ar, N5-1)*N5;

    float4 aR[4], bR[BCNT];

    auto loadRegs = [&](int c){
        const int k0 = kbase + c*32;
#pragma unroll
        for (int j = 0; j < 4; j++) aR[j] = *(const float4*)&aptr[k0 + aseg*16 + j*4];
#pragma unroll
        for (int i = 0; i < BCNT; i++){
            int idx = t + i*256;
            int br = idx/NB4, bc = idx%NB4;
            int gk = k0 + br;
            bR[i] = (gk < kend) ? *(const float4*)&Pk[(size_t)gk*BN + bc*4]
                                : make_float4(0,0,0,0);
        }
    };
    auto storeTiles = [&](int s){
        unsigned* As = Asm + s*ASZ;
        unsigned* Bs = Bsm + s*BSZ;
#pragma unroll
        for (int j = 0; j < 4; j++){
            int col = aseg*16 + j*4;
            As[(col+0)*136 + ar] = uf(aR[j].x);
            As[(col+1)*136 + ar] = uf(aR[j].y);
            As[(col+2)*136 + ar] = uf(aR[j].z);
            As[(col+3)*136 + ar] = uf(aR[j].w);
        }
#pragma unroll
        for (int i = 0; i < BCNT; i++){
            int idx = t + i*256;
            int br = idx/NB4, bc = idx%NB4;
            *(uint4*)&Bs[br*BP + bc*4] = *(uint4*)&bR[i];
        }
    };

    float acc[2][NT][4];
#pragma unroll
    for (int mt = 0; mt < 2; mt++)
#pragma unroll
        for (int nt = 0; nt < NT; nt++)
#pragma unroll
            for (int q = 0; q < 4; q++) acc[mt][nt][q] = 0.f;

    loadRegs(0);
    storeTiles(0);
    if (nch > 1) loadRegs(1);
    __syncthreads();

    for (int c = 0; c < nch; c++){
        const int s = c & 1;
        if (c+1 < nch) storeTiles(s^1);       // regs hold chunk c+1
        if (c+2 < nch) loadRegs(c+2);         // overlap global with MMA
        const unsigned* As = Asm + s*ASZ;
        const unsigned* Bs = Bsm + s*BSZ;
#pragma unroll
        for (int kk = 0; kk < 4; kk++){
            const int k = kk*8;
            unsigned a[2][4];
#pragma unroll
            for (int mt = 0; mt < 2; mt++){
                int m0 = wm*32 + mt*16;
                a[mt][0]=As[(k+ctg)*136 + m0+g];   a[mt][1]=As[(k+ctg)*136 + m0+g+8];
                a[mt][2]=As[(k+ctg+4)*136 + m0+g]; a[mt][3]=As[(k+ctg+4)*136 + m0+g+8];
            }
#pragma unroll
            for (int nt = 0; nt < NT; nt++){
                int n = wn*(BN/2) + nt*8 + g;
                unsigned b0 = Bs[(k+ctg)*BP + n], b1 = Bs[(k+ctg+4)*BP + n];
                mma8(acc[0][nt], a[0], b0, b1);
                mma8(acc[1][nt], a[1], b0, b1);
            }
        }
        __syncthreads();
    }

    float* dst = g_part + (size_t)y*N5*BN;
#pragma unroll
    for (int mt = 0; mt < 2; mt++){
#pragma unroll
        for (int nt = 0; nt < NT; nt++){
            int i0 = bi*128 + wm*32 + mt*16 + g;
            int n  = wn*(BN/2) + nt*8 + ctg*2;
            if (i0 < N5)
                *(float2*)&dst[(size_t)i0*BN + n] =
                    make_float2(acc[mt][nt][0], acc[mt][nt][1]);
            if (i0+8 < N5)
                *(float2*)&dst[(size_t)(i0+8)*BN + n] =
                    make_float2(acc[mt][nt][2], acc[mt][nt][3]);
        }
    }
}

// ---------------- fused: g_base = elu(g_acc + 16 partials), col min/max partials ------
template<int C>
__global__ void k_winred_mm()
{
    __shared__ float smn[4][128], smx[4][128];
    const int t = threadIdx.x;
    const int c = t % C, rp = t / C;
    const int r0 = blockIdx.x*25;
    float mn = 3.4e38f, mx = -3.4e38f;
    for (int r = rp; r < 25; r += 4){
        size_t idx = (size_t)(r0 + r)*C + c;
        float v = g_acc[idx];
#pragma unroll
        for (int s = 0; s < 16; s++) v += g_part[(size_t)s*N5*C + idx];
        v = eluf(v);
        g_base[idx] = v;
        mn = fminf(mn, v); mx = fmaxf(mx, v);
    }
    smn[rp][c] = mn; smx[rp][c] = mx;
    __syncthreads();
    if (rp == 0){
        mn = fminf(fminf(smn[0][c], smn[1][c]), fminf(smn[2][c], smn[3][c]));
        mx = fmaxf(fmaxf(smx[0][c], smx[1][c]), fmaxf(smx[2][c], smx[3][c]));
        g_mnp[blockIdx.x*128 + c] = mn;
        g_mxp[blockIdx.x*128 + c] = mx;
    }
}

// ---------------- fc2_w elementwise tf32 round ----------------
__global__ void k_fc2r(const float* __restrict__ B)
{
    int idx = blockIdx.x*blockDim.x + threadIdx.x;
    if (idx < 256*N5) g_fc2r[idx] = tf32rf(B[idx]);
}

// ---------------- logits = des @ fc2_w + fc2_b ----------------
__global__ __launch_bounds__(256,2) void k_linear_tc(const float* __restrict__ bias,
                                                     float* __restrict__ out)
{
    __shared__ unsigned As[32][136];
    __shared__ __align__(16) unsigned Bs[32][136];

    const int t = threadIdx.x;
    const int w = t >> 5, lane = t & 31, g = lane >> 2, ctg = lane & 3;
    const int wm = w >> 1, wn = w & 1;
    const int bi = blockIdx.y, bj = blockIdx.x;
    const int ar = t >> 1, aseg = t & 1;
    const float* aptr = g_desr + (size_t)min(bi*128 + ar, N5-1)*256;

    float acc[2][8][4];
#pragma unroll
    for (int mt = 0; mt < 2; mt++)
#pragma unroll
        for (int nt = 0; nt < 8; nt++)
#pragma unroll
            for (int q = 0; q < 4; q++) acc[mt][nt][q] = 0.f;

    for (int c = 0; c < 8; c++){
        const int k0 = c*32;
        __syncthreads();
#pragma unroll
        for (int j = 0; j < 4; j++){
            int col = aseg*16 + j*4;
            float4 v = *(const float4*)&aptr[k0 + col];
            As[col+0][ar] = uf(v.x);
            As[col+1][ar] = uf(v.y);
            As[col+2][ar] = uf(v.z);
            As[col+3][ar] = uf(v.w);
        }
#pragma unroll
        for (int i = 0; i < 4; i++){
            int idx = t + i*256;
            int br = idx >> 5, bc = idx & 31;
            int gj = bj*128 + bc*4;
            float4 v;
            if (gj + 3 < N5) v = *(const float4*)&g_fc2r[(size_t)(k0+br)*N5 + gj];
            else {
                v = make_float4(0,0,0,0);
                if (gj+0 < N5) v.x = g_fc2r[(size_t)(k0+br)*N5 + gj+0];
                if (gj+1 < N5) v.y = g_fc2r[(size_t)(k0+br)*N5 + gj+1];
                if (gj+2 < N5) v.z = g_fc2r[(size_t)(k0+br)*N5 + gj+2];
                if (gj+3 < N5) v.w = g_fc2r[(size_t)(k0+br)*N5 + gj+3];
            }
            *(uint4*)&Bs[br][bc*4] = *(uint4*)&v;
        }
        __syncthreads();
#pragma unroll
        for (int kk = 0; kk < 4; kk++){
            const int k = kk*8;
            unsigned a[2][4];
#pragma unroll
            for (int mt = 0; mt < 2; mt++){
                int m0 = wm*32 + mt*16;
                a[mt][0]=As[k+ctg][m0+g];   a[mt][1]=As[k+ctg][m0+g+8];
                a[mt][2]=As[k+ctg+4][m0+g]; a[mt][3]=As[k+ctg+4][m0+g+8];
            }
#pragma unroll
            for (int nt = 0; nt < 8; nt++){
                int n = wn*64 + nt*8 + g;
                unsigned b0 = Bs[k+ctg][n], b1 = Bs[k+ctg+4][n];
                mma8(acc[0][nt], a[0], b0, b1);
                mma8(acc[1][nt], a[1], b0, b1);
            }
        }
    }
#pragma unroll
    for (int mt = 0; mt < 2; mt++){
#pragma unroll
        for (int nt = 0; nt < 8; nt++){
            int i0 = bi*128 + wm*32 + mt*16 + g;
            int jb = bj*128 + wn*64 + nt*8 + ctg*2;
            float b0 = (jb   < N5) ? bias[jb]   : 0.f;
            float b1 = (jb+1 < N5) ? bias[jb+1] : 0.f;
            if (i0 < N5 && jb < N5){
                if (jb+1 < N5)
                    *(float2*)&out[(size_t)i0*N5 + jb] =
                        make_float2(acc[mt][nt][0]+b0, acc[mt][nt][1]+b1);
                else out[(size_t)i0*N5 + jb] = acc[mt][nt][0]+b0;
            }
            if (i0+8 < N5 && jb < N5){
                if (jb+1 < N5)
                    *(float2*)&out[(size_t)(i0+8)*N5 + jb] =
                        make_float2(acc[mt][nt][2]+b0, acc[mt][nt][3]+b1);
                else out[(size_t)(i0+8)*N5 + jb] = acc[mt][nt][2]+b0;
            }
        }
    }
}

// ---------------- log-softmax, register-resident ----------------
__global__ void k_logsoftmax(float* __restrict__ out)
{
    const int row = blockIdx.x;
    float* p = out + (size_t)row*N5;
    const int t = threadIdx.x;
    float4 v[5];
    bool have[5];
    float mx = -3.4e38f;
#pragma unroll
    for (int s = 0; s < 5; s++){
        int i4 = t + s*256;
        have[s] = i4 < 1250;
        if (have[s]){
            v[s] = *(const float4*)&p[i4*4];
            mx = fmaxf(mx, fmaxf(fmaxf(v[s].x, v[s].y), fmaxf(v[s].z, v[s].w)));
        }
    }
    __shared__ float sh[256];
    sh[t] = mx; __syncthreads();
    for (int s = 128; s > 0; s >>= 1){
        if (t < s) sh[t] = fmaxf(sh[t], sh[t+s]);
        __syncthreads();
    }
    mx = sh[0]; __syncthreads();
    float sum = 0.f;
#pragma unroll
    for (int s = 0; s < 5; s++)
        if (have[s])
            sum += expf(v[s].x-mx) + expf(v[s].y-mx) + expf(v[s].z-mx) + expf(v[s].w-mx);
    sh[t] = sum; __syncthreads();
    for (int s = 128; s > 0; s >>= 1){
        if (t < s) sh[t] += sh[t+s];
        __syncthreads();
    }
    float lse = mx + logf(sh[0]);
#pragma unroll
    for (int s = 0; s < 5; s++){
        if (have[s]){
            int i4 = t + s*256;
            *(float4*)&p[i4*4] = make_float4(v[s].x-lse, v[s].y-lse, v[s].z-lse, v[s].w-lse);
        }
    }
}

__global__ void k_copydes(float* __restrict__ out)
{
    int total = N5*256;
    for (int idx = blockIdx.x*blockDim.x + threadIdx.x; idx < total;
         idx += gridDim.x*blockDim.x)
        out[idx] = g_des[idx];
}

// ---------------- launcher ----------------
extern "C" void kernel_launch(void* const* d_in, const int* in_sizes, int n_in,
                              void* d_out, int out_size)
{
    (void)in_sizes; (void)n_in;
    const float* x    = (const float*)d_in[0];
    const float* V    = (const float*)d_in[1];
    const float* A    = (const float*)d_in[2];
    const float* clk  = (const float*)d_in[3];
    const float* Wc[6] = {(const float*)d_in[4], (const float*)d_in[5],
                          (const float*)d_in[6], (const float*)d_in[7],
                          (const float*)d_in[8], (const float*)d_in[9]};
    const float* fc1w = (const float*)d_in[10];
    const float* fc1b = (const float*)d_in[11];
    const float* fc2w = (const float*)d_in[12];
    const float* fc2b = (const float*)d_in[13];
    float* out = (float*)d_out;

    const int smWin96  = (2*32*136 + 2*32*104)*4;   // 61440
    const int smWin128 = (2*32*136 + 2*32*136)*4;   // 69632
    cudaFuncSetAttribute(k_winapply_tc<96>,  cudaFuncAttributeMaxDynamicSharedMemorySize, smWin96);
    cudaFuncSetAttribute(k_winapply_tc<128>, cudaFuncAttributeMaxDynamicSharedMemorySize, smWin128);

    // preamble
    k_clkz<<<1,256>>>(clk);
    k_mm_part<<<200,512>>>(x, 128);
    k_colfin<<<1,128>>>(128);

    // Build Win (tf32-rounded M^2, symmetric tiles) + column norms -> icol2
    k_build_sym<<<dim3(820,4),256>>>(A, V);
    k_colreduce<<<dim3(20,4),256>>>();

    // Layer 1: 128 -> 96  (proj normalizes x inline)
    k_proj_tc<128,96><<<dim3(40,5),256>>>(Wc[0], x);
    k_winapply_tc<96><<<dim3(40,16),256,smWin96>>>();
    k_winred_mm<96><<<200,384>>>();
    k_colfin<<<1,128>>>(96);

    // Layers 2-5: 96 -> 96
    for (int L = 1; L < 5; L++){
        k_proj_tc<96,96><<<dim3(40,5),256>>>(Wc[L], nullptr);
        k_winapply_tc<96><<<dim3(40,16),256,smWin96>>>();
        k_winred_mm<96><<<200,384>>>();
        k_colfin<<<1,128>>>(96);
    }

    // Layer 6: 96 -> 128
    k_proj_tc<96,128><<<dim3(40,5),256>>>(Wc[5], nullptr);
    k_winapply_tc<128><<<dim3(40,16),256,smWin128>>>();
    k_winred_mm<128><<<200,512>>>();
    k_colfin<<<1,128>>>(128);

    // des = elu(fmaxmin(h) @ fc1_w + fc1_b)
    k_proj_des<128,256><<<79,256>>>(fc1w, fc1b);

    // logits + log_softmax
    k_fc2r<<<5000,256>>>(fc2w);
    k_linear_tc<<<dim3(40,40),256>>>(fc2b, out);
    k_logsoftmax<<<5000,256>>>(out);

    // second output: des
    if (out_size >= 25000000 + N5*256)
        k_copydes<<<640,256>>>(out + 25000000);
}

// round 15
// speedup vs baseline: 1.2242x; 1.0051x over previous
#include <cuda_runtime.h>
#include <math.h>
#include <stdint.h>

#define N5 5000

// ---------------- scratch (device globals; no allocation allowed) ----------------
__device__ float g_win[100000032];        // [4][5000][5000] (+pad) = M^2, tf32-rounded
__device__ float g_colpart[4*40*5000];
__device__ float g_icol2[4*5000];
__device__ float g_base[5000*128];        // layer activations (post-elu), proj INPUT only
__device__ float g_acc[5000*128];         // base term h@W0 (proj j==0 output)
__device__ float g_P[4*5000*128];         // P_k [k][n], tf32-rounded, icol2 folded
__device__ float g_part[16*5000*128];     // split-K partials (16 chunks)
__device__ float g_desr[5000*256];        // tf32-rounded des for logits MMA
__device__ float g_clkz[4*256];           // clk column per z
__device__ float g_mnp[200*128];
__device__ float g_mxp[200*128];
__device__ float g_nmn[128];
__device__ float g_nd[128];

__device__ __forceinline__ float eluf(float v){ return v > 0.f ? v : expm1f(v); }

__device__ __forceinline__ unsigned tf32r(float f){
    unsigned u; asm("cvt.rna.tf32.f32 %0, %1;" : "=r"(u) : "f"(f)); return u;
}
__device__ __forceinline__ float tf32rf(float f){ return __uint_as_float(tf32r(f)); }
__device__ __forceinline__ void splitf(float v, unsigned& hi, unsigned& lo){
    unsigned h = tf32r(v);
    lo = tf32r(v - __uint_as_float(h));
    hi = h;
}
__device__ __forceinline__ unsigned uf(float f){ return __float_as_uint(f); }
__device__ __forceinline__ void mma8(float* c, const unsigned* a, unsigned b0, unsigned b1){
    asm volatile("mma.sync.aligned.m16n8k8.row.col.f32.tf32.tf32.f32 "
        "{%0,%1,%2,%3},{%4,%5,%6,%7},{%8,%9},{%0,%1,%2,%3};"
        : "+f"(c[0]),"+f"(c[1]),"+f"(c[2]),"+f"(c[3])
        : "r"(a[0]),"r"(a[1]),"r"(a[2]),"r"(a[3]),"r"(b0),"r"(b1));
}

// ---------------- clk column pack ----------------
__global__ void k_clkz(const float* __restrict__ clk)
{
    int e = threadIdx.x;
#pragma unroll
    for (int z = 0; z < 4; z++)
        g_clkz[z*256 + e] = clk[e*32 + (31 - 8*z)];
}

// ---------------- coalesced per-column min/max partials (input x only) ----------------
__global__ void k_mm_part(const float* __restrict__ src, int C)
{
    __shared__ float smn[4][128], smx[4][128];
    const int t = threadIdx.x;
    const int c = t % C, rp = t / C;
    const int r0 = blockIdx.x*25;
    float mn = 3.4e38f, mx = -3.4e38f;
    for (int r = rp; r < 25; r += 4){
        float v = src[(size_t)(r0 + r)*C + c];
        mn = fminf(mn, v); mx = fmaxf(mx, v);
    }
    smn[rp][c] = mn; smx[rp][c] = mx;
    __syncthreads();
    if (rp == 0){
        mn = fminf(fminf(smn[0][c], smn[1][c]), fminf(smn[2][c], smn[3][c]));
        mx = fmaxf(fmaxf(smx[0][c], smx[1][c]), fmaxf(smx[2][c], smx[3][c]));
        g_mnp[blockIdx.x*128 + c] = mn;
        g_mxp[blockIdx.x*128 + c] = mx;
    }
}

// finalize per-column norm constants (same b-ascending order as before)
__global__ void k_colfin(int C)
{
    int c = threadIdx.x;
    if (c < C){
        float mn = 3.4e38f, mx = -3.4e38f;
        for (int b = 0; b < 200; b++){
            mn = fminf(mn, g_mnp[b*128 + c]);
            mx = fmaxf(mx, g_mxp[b*128 + c]);
        }
        g_nmn[c] = mn;
        g_nd[c]  = mx - mn;
    }
}

// ---------------- build Win, SYMMETRIC (inline split + reg prefetch; R10-proven) --------
__global__ __launch_bounds__(256,2) void k_build_sym(const float* __restrict__ A,
                                                     const float* __restrict__ V)
{
    __shared__ unsigned smemAB[4][16][136];
    __shared__ float scol[4][128];
    __shared__ float msum[2][128];
    unsigned (*Ah)[136] = smemAB[0];
    unsigned (*Al)[136] = smemAB[1];
    unsigned (*Bh)[136] = smemAB[2];
    unsigned (*Bl)[136] = smemAB[3];
    float (*tr)[132] = (float(*)[132])(&smemAB[0][0][0]);  // 32x132 fits in Ah+Al

    const int z = blockIdx.y;
    int bi = 0, rem = blockIdx.x;
    while (rem >= 40 - bi){ rem -= 40 - bi; bi++; }
    const int bj = bi + rem;

    const int t = threadIdx.x;
    const int w = t >> 5, lane = t & 31, g = lane >> 2, ctg = lane & 3;
    const int wm = w >> 1, wn = w & 1;
    const int r = t >> 1, seg = t & 1;
    const int garow = min(bi*128 + r, N5-1);
    const int gbrow = min(bj*128 + r, N5-1);
    const float* vaRow = V + (size_t)garow*256;
    const float* vbRow = V + (size_t)gbrow*256;
    const float* ck = g_clkz + z*256;

    float4 Pva[2], Pvb[2], Pck[2];
#pragma unroll
    for (int j = 0; j < 2; j++){
        int col = seg*8 + j*4;
        Pva[j] = *(const float4*)&vaRow[col];
        Pvb[j] = *(const float4*)&vbRow[col];
        Pck[j] = *(const float4*)&ck[col];
    }

    float acc[2][8][4];
#pragma unroll
    for (int mt = 0; mt < 2; mt++)
#pragma unroll
        for (int nt = 0; nt < 8; nt++)
#pragma unroll
            for (int q = 0; q < 4; q++) acc[mt][nt][q] = 0.f;

    for (int c = 0; c < 16; c++){
        __syncthreads();
#pragma unroll
        for (int j = 0; j < 2; j++){
            int col = seg*8 + j*4;
            unsigned h, l;
            splitf(Pva[j].x*Pck[j].x, h, l); Ah[col+0][r]=h; Al[col+0][r]=l;
            splitf(Pva[j].y*Pck[j].y, h, l); Ah[col+1][r]=h; Al[col+1][r]=l;
            splitf(Pva[j].z*Pck[j].z, h, l); Ah[col+2][r]=h; Al[col+2][r]=l;
            splitf(Pva[j].w*Pck[j].w, h, l); Ah[col+3][r]=h; Al[col+3][r]=l;
            splitf(Pvb[j].x, h, l); Bh[col+0][r]=h; Bl[col+0][r]=l;
            splitf(Pvb[j].y, h, l); Bh[col+1][r]=h; Bl[col+1][r]=l;
            splitf(Pvb[j].z, h, l); Bh[col+2][r]=h; Bl[col+2][r]=l;
            splitf(Pvb[j].w, h, l); Bh[col+3][r]=h; Bl[col+3][r]=l;
        }
        if (c+1 < 16){
            const int k0 = (c+1)*16;
#pragma unroll
            for (int j = 0; j < 2; j++){
                int col = k0 + seg*8 + j*4;
                Pva[j] = *(const float4*)&vaRow[col];
                Pvb[j] = *(const float4*)&vbRow[col];
                Pck[j] = *(const float4*)&ck[col];
            }
        }
        __syncthreads();
#pragma unroll
        for (int kk = 0; kk < 2; kk++){
            const int k = kk*8;
            unsigned ah[2][4], al[2][4];
#pragma unroll
            for (int mt = 0; mt < 2; mt++){
                int m0 = wm*32 + mt*16;
                ah[mt][0]=Ah[k+ctg][m0+g];   ah[mt][1]=Ah[k+ctg][m0+g+8];
                ah[mt][2]=Ah[k+ctg+4][m0+g]; ah[mt][3]=Ah[k+ctg+4][m0+g+8];
                al[mt][0]=Al[k+ctg][m0+g];   al[mt][1]=Al[k+ctg][m0+g+8];
                al[mt][2]=Al[k+ctg+4][m0+g]; al[mt][3]=Al[k+ctg+4][m0+g+8];
            }
#pragma unroll
            for (int nt = 0; nt < 8; nt++){
                int n = wn*64 + nt*8 + g;
                unsigned bh0 = Bh[k+ctg][n], bh1 = Bh[k+ctg+4][n];
                unsigned bl0 = Bl[k+ctg][n], bl1 = Bl[k+ctg+4][n];
#pragma unroll
                for (int mt = 0; mt < 2; mt++){
                    mma8(acc[mt][nt], ah[mt], bh0, bh1);
                    mma8(acc[mt][nt], ah[mt], bl0, bl1);
                    mma8(acc[mt][nt], al[mt], bh0, bh1);
                }
            }
        }
    }

    const size_t zbase = (size_t)z*25000000;

    // normal tile: store tf32-rounded X; colpart from exact X
#pragma unroll
    for (int nt = 0; nt < 8; nt++){
        int jb = bj*128 + wn*64 + nt*8 + ctg*2;
        float aj0 = (jb   < N5) ? A[jb]   : 0.f;
        float aj1 = (jb+1 < N5) ? A[jb+1] : 0.f;
        float se = 0.f, so = 0.f;
#pragma unroll
        for (int mt = 0; mt < 2; mt++){
            int i0 = bi*128 + wm*32 + mt*16 + g;
            float m00 = acc[mt][nt][0]*aj0; float X00 = m00*m00; X00 *= X00;
            float m01 = acc[mt][nt][1]*aj1; float X01 = m01*m01; X01 *= X01;
            float m10 = acc[mt][nt][2]*aj0; float X10 = m10*m10; X10 *= X10;
            float m11 = acc[mt][nt][3]*aj1; float X11 = m11*m11; X11 *= X11;
            bool ok0 = i0 < N5, ok1 = (i0+8) < N5;
            if (ok0 && jb < N5){
                if (jb+1 < N5) *(float2*)&g_win[zbase + (size_t)i0*N5 + jb] =
                                   make_float2(tf32rf(X00), tf32rf(X01));
                else g_win[zbase + (size_t)i0*N5 + jb] = tf32rf(X00);
            }
            if (ok1 && jb < N5){
                if (jb+1 < N5) *(float2*)&g_win[zbase + (size_t)(i0+8)*N5 + jb] =
                                   make_float2(tf32rf(X10), tf32rf(X11));
                else g_win[zbase + (size_t)(i0+8)*N5 + jb] = tf32rf(X10);
            }
            se += (ok0?X00:0.f) + (ok1?X10:0.f);
            so += (ok0?X01:0.f) + (ok1?X11:0.f);
        }
#pragma unroll
        for (int off = 4; off < 32; off <<= 1){
            se += __shfl_xor_sync(0xffffffffu, se, off);
            so += __shfl_xor_sync(0xffffffffu, so, off);
        }
        if (lane < 4){
            scol[wm][wn*64 + nt*8 + lane*2]     = se;
            scol[wm][wn*64 + nt*8 + lane*2 + 1] = so;
        }
    }
    __syncthreads();
    if (t < 128){
        float s = scol[0][t] + scol[1][t] + scol[2][t] + scol[3][t];
        int j = bj*128 + t;
        if (j < N5) g_colpart[((size_t)z*40 + bi)*N5 + j] = s;
    }

    if (bi == bj) return;

    // mirror tile
    float ai[2][2];
#pragma unroll
    for (int mt = 0; mt < 2; mt++){
        int i0 = bi*128 + wm*32 + mt*16 + g;
        ai[mt][0] = A[i0];
        ai[mt][1] = A[i0+8];
    }

    float rs[2][2] = {{0.f,0.f},{0.f,0.f}};
#pragma unroll
    for (int nt = 0; nt < 8; nt++){
        int jb = bj*128 + wn*64 + nt*8 + ctg*2;
        bool j0ok = jb < N5, j1ok = (jb+1) < N5;
#pragma unroll
        for (int mt = 0; mt < 2; mt++){
            float m00 = acc[mt][nt][0]*ai[mt][0]; float X00 = m00*m00; X00 *= X00;
            float m01 = acc[mt][nt][1]*ai[mt][0]; float X01 = m01*m01; X01 *= X01;
            float m10 = acc[mt][nt][2]*ai[mt][1]; float X10 = m10*m10; X10 *= X10;
            float m11 = acc[mt][nt][3]*ai[mt][1]; float X11 = m11*m11; X11 *= X11;
            rs[mt][0] += (j0ok?X00:0.f) + (j1ok?X01:0.f);
            rs[mt][1] += (j0ok?X10:0.f) + (j1ok?X11:0.f);
        }
    }
#pragma unroll
    for (int off = 1; off < 4; off <<= 1){
#pragma unroll
        for (int mt = 0; mt < 2; mt++){
            rs[mt][0] += __shfl_xor_sync(0xffffffffu, rs[mt][0], off);
            rs[mt][1] += __shfl_xor_sync(0xffffffffu, rs[mt][1], off);
        }
    }
    if (ctg == 0){
#pragma unroll
        for (int mt = 0; mt < 2; mt++){
            if (wn == 0){
                msum[0][wm*32 + mt*16 + g]     = rs[mt][0];
                msum[0][wm*32 + mt*16 + g + 8] = rs[mt][1];
            } else {
                msum[1][wm*32 + mt*16 + g]     = rs[mt][0];
                msum[1][wm*32 + mt*16 + g + 8] = rs[mt][1];
            }
        }
    }
    __syncthreads();
    if (t < 128)
        g_colpart[((size_t)z*40 + bj)*N5 + bi*128 + t] = msum[0][t] + msum[1][t];

    // staged transpose write of mirror tile, 4 chunks of 32 j-rows
    for (int c = 0; c < 4; c++){
        __syncthreads();
        if (wn == (c >> 1)){
#pragma unroll
            for (int q = 0; q < 4; q++){
                int nt = (c & 1)*4 + q;
                int jl = nt*8 + ctg*2 - (c & 1)*32;
#pragma unroll
                for (int mt = 0; mt < 2; mt++){
                    int il = wm*32 + mt*16 + g;
                    float m00 = acc[mt][nt][0]*ai[mt][0]; float X00 = m00*m00; X00 *= X00;
                    float m01 = acc[mt][nt][1]*ai[mt][0]; float X01 = m01*m01; X01 *= X01;
                    float m10 = acc[mt][nt][2]*ai[mt][1]; float X10 = m10*m10; X10 *= X10;
                    float m11 = acc[mt][nt][3]*ai[mt][1]; float X11 = m11*m11; X11 *= X11;
                    tr[jl  ][il]   = tf32rf(X00);
                    tr[jl  ][il+8] = tf32rf(X10);
                    tr[jl+1][il]   = tf32rf(X01);
                    tr[jl+1][il+8] = tf32rf(X11);
                }
            }
        }
        __syncthreads();
        int jg0 = bj*128 + c*32;
        for (int idx = t; idx < 32*32; idx += 256){
            int row = idx >> 5, c4 = (idx & 31)*4;
            int jg = jg0 + row;
            if (jg < N5)
                *(float4*)&g_win[zbase + (size_t)jg*N5 + bi*128 + c4] =
                    *(float4*)&tr[row][c4];
        }
    }
}

__global__ void k_colreduce()
{
    int z = blockIdx.y;
    int j = blockIdx.x*blockDim.x + threadIdx.x;
    if (j < N5){
        float s = 0.f;
        for (int b = 0; b < 40; b++) s += g_colpart[((size_t)z*40 + b)*N5 + j];
        float c = fmaxf(sqrtf(s), 1e-12f);
        g_icol2[z*N5 + j] = 1.0f/(c*c);
    }
}

// ---------------- tensor-core proj, inline fmaxmin via g_nmn/g_nd ----------------
// reads src (x or g_base), writes g_acc (j==0) / g_P (j>0). No aliasing.
template<int CI, int CO>
__global__ __launch_bounds__(256,2) void k_proj_tc(const float* __restrict__ W,
                                                   const float* __restrict__ xsrc)
{
    constexpr int NT = CO/16;
    __shared__ unsigned Hh[128][17], Hl[128][17];
    __shared__ unsigned Ws[16][CO+4];
    __shared__ float nmn[CI], nd[CI];

    const float* src = xsrc ? xsrc : g_base;
    const int j = blockIdx.y;
    const float* Wj = W + (size_t)j*CI*CO;
    const int r0 = blockIdx.x*128;
    const int t = threadIdx.x;
    const int w = t >> 5, lane = t & 31, g = lane >> 2, ctg = lane & 3;
    const int wm = w >> 1, wn = w & 1;

    for (int c = t; c < CI; c += 256){
        nmn[c] = g_nmn[c];
        nd[c]  = g_nd[c];
    }

    float acc[2][NT][4];
#pragma unroll
    for (int mt = 0; mt < 2; mt++)
#pragma unroll
        for (int nt = 0; nt < NT; nt++)
#pragma unroll
            for (int q = 0; q < 4; q++) acc[mt][nt][q] = 0.f;

    for (int c0 = 0; c0 < CI; c0 += 16){
        __syncthreads();
#pragma unroll
        for (int i = 0; i < 2; i++){
            int idx = t + i*256;
            int m = idx >> 2, k4 = (idx & 3)*4;
            int gr = min(r0 + m, N5-1);
            float4 v = *(const float4*)&src[(size_t)gr*CI + c0 + k4];
            v.x = (v.x - nmn[c0+k4+0]) / nd[c0+k4+0];
            v.y = (v.y - nmn[c0+k4+1]) / nd[c0+k4+1];
            v.z = (v.z - nmn[c0+k4+2]) / nd[c0+k4+2];
            v.w = (v.w - nmn[c0+k4+3]) / nd[c0+k4+3];
            unsigned h0,l0;
            splitf(v.x,h0,l0); Hh[m][k4+0]=h0; Hl[m][k4+0]=l0;
            splitf(v.y,h0,l0); Hh[m][k4+1]=h0; Hl[m][k4+1]=l0;
            splitf(v.z,h0,l0); Hh[m][k4+2]=h0; Hl[m][k4+2]=l0;
            splitf(v.w,h0,l0); Hh[m][k4+3]=h0; Hl[m][k4+3]=l0;
        }
        for (int idx = t; idx < 16*CO; idx += 256){
            int kk2 = idx / CO, o = idx % CO;
            Ws[kk2][o] = tf32r(Wj[(size_t)(c0+kk2)*CO + o]);
        }
        __syncthreads();
#pragma unroll
        for (int kk = 0; kk < 2; kk++){
            const int k = kk*8;
            unsigned ah[2][4], al[2][4];
#pragma unroll
            for (int mt = 0; mt < 2; mt++){
                int m0 = wm*32 + mt*16;
                ah[mt][0]=Hh[m0+g][k+ctg];   ah[mt][1]=Hh[m0+g+8][k+ctg];
                ah[mt][2]=Hh[m0+g][k+ctg+4]; ah[mt][3]=Hh[m0+g+8][k+ctg+4];
                al[mt][0]=Hl[m0+g][k+ctg];   al[mt][1]=Hl[m0+g+8][k+ctg];
                al[mt][2]=Hl[m0+g][k+ctg+4]; al[mt][3]=Hl[m0+g+8][k+ctg+4];
            }
#pragma unroll
            for (int nt = 0; nt < NT; nt++){
                int n = wn*(CO/2) + nt*8 + g;
                unsigned b0 = Ws[k+ctg][n], b1 = Ws[k+ctg+4][n];
#pragma unroll
                for (int mt = 0; mt < 2; mt++){
                    mma8(acc[mt][nt], ah[mt], b0, b1);
                    mma8(acc[mt][nt], al[mt], b0, b1);
                }
            }
        }
    }

#pragma unroll
    for (int mt = 0; mt < 2; mt++){
        int i0 = r0 + wm*32 + mt*16 + g;
        if (j == 0){
#pragma unroll
            for (int nt = 0; nt < NT; nt++){
                int n = wn*(CO/2) + nt*8 + ctg*2;
                if (i0 < N5)
                    *(float2*)&g_acc[(size_t)i0*CO + n] =
                        make_float2(acc[mt][nt][0], acc[mt][nt][1]);
                if (i0+8 < N5)
                    *(float2*)&g_acc[(size_t)(i0+8)*CO + n] =
                        make_float2(acc[mt][nt][2], acc[mt][nt][3]);
            }
        } else {
            float s0 = (i0   < N5) ? g_icol2[(j-1)*N5 + i0]   : 0.f;
            float s8 = (i0+8 < N5) ? g_icol2[(j-1)*N5 + i0+8] : 0.f;
            float* P = g_P + (size_t)(j-1)*N5*CO;
#pragma unroll
            for (int nt = 0; nt < NT; nt++){
                int n = wn*(CO/2) + nt*8 + ctg*2;
                if (i0 < N5)
                    *(float2*)&P[(size_t)i0*CO + n] =
                        make_float2(tf32rf(acc[mt][nt][0]*s0), tf32rf(acc[mt][nt][1]*s0));
                if (i0+8 < N5)
                    *(float2*)&P[(size_t)(i0+8)*CO + n] =
                        make_float2(tf32rf(acc[mt][nt][2]*s8), tf32rf(acc[mt][nt][3]*s8));
            }
        }
    }
}

// ---------------- SIMT proj for des (bias + elu), inline normalization ----------
// writes tf32-rounded copy to g_desr; exact values directly to desout (if non-null)
template<int CI, int CO>
__global__ __launch_bounds__(256) void k_proj_des(const float* __restrict__ W,
                                                  const float* __restrict__ bias,
                                                  float* __restrict__ desout)
{
    constexpr int PER = (64*CO)/256;
    const int r0 = blockIdx.x*64;
    const int t = threadIdx.x;

    __shared__ float ht[64][33];
    __shared__ float Wt[32][CO+1];
    __shared__ float nmn[CI], nd[CI];

    for (int c = t; c < CI; c += 256){
        nmn[c] = g_nmn[c];
        nd[c]  = g_nd[c];
    }
    __syncthreads();

    float acc[PER];
#pragma unroll
    for (int p = 0; p < PER; p++) acc[p] = 0.f;

    for (int c0 = 0; c0 < CI; c0 += 32){
        for (int idx = t; idx < 64*32; idx += 256){
            int r = idx >> 5, cc = idx & 31;
            int gr = r0 + r;
            float v = 0.f;
            if (gr < N5)
                v = (g_base[(size_t)gr*CI + c0 + cc] - nmn[c0+cc]) / nd[c0+cc];
            ht[r][cc] = v;
        }
        for (int idx = t; idx < 32*CO; idx += 256){
            int cc = idx / CO, o = idx % CO;
            Wt[cc][o] = W[(size_t)(c0+cc)*CO + o];
        }
        __syncthreads();
#pragma unroll
        for (int p = 0; p < PER; p++){
            int oi = t + p*256;
            int rr = oi / CO, o = oi % CO;
            float s = acc[p];
#pragma unroll
            for (int cc = 0; cc < 32; cc++) s += ht[rr][cc]*Wt[cc][o];
            acc[p] = s;
        }
        __syncthreads();
    }
#pragma unroll
    for (int p = 0; p < PER; p++){
        int oi = t + p*256;
        int rr = oi / CO, o = oi % CO;
        int gr = r0 + rr;
        if (gr < N5){
            float v = eluf(acc[p] + bias[o]);
            g_desr[(size_t)gr*CO + o] = tf32rf(v);
            if (desout) desout[(size_t)gr*CO + o] = v;
        }
    }
}

// ---------------- winapply: double-buffered, split-K 16 (1248-aligned; R10-proven) ------
template<int BN>
__global__ __launch_bounds__(256,2) void k_winapply_tc()
{
    constexpr int BP = (BN==96) ? 104 : 136;
    constexpr int NT = BN/16;
    constexpr int NB4 = BN/4;
    constexpr int BCNT = (32*NB4)/256;
    constexpr int ASZ = 32*136;
    constexpr int BSZ = 32*BP;
    extern __shared__ __align__(16) unsigned smemU[];   // As[2][32][136], Bs[2][32][BP]
    unsigned* Asm = smemU;
    unsigned* Bsm = smemU + 2*ASZ;

    const int t = threadIdx.x;
    const int w = t >> 5, lane = t & 31, g = lane >> 2, ctg = lane & 3;
    const int wm = w >> 1, wn = w & 1;
    const int bi = blockIdx.x, y = blockIdx.y;
    const int slab = y >> 2;
    const int part = y & 3;
    const int kbase = part*1248;
    const int kend  = (part == 3) ? N5 : kbase + 1248;
    const int nch   = (part == 3) ? 40 : 39;
    const float* __restrict__ Wk = g_win + (size_t)slab*25000000;
    const float* __restrict__ Pk = g_P + (size_t)slab*N5*BN;
    const int ar = t >> 1, aseg = t & 1;
    const float* aptr = Wk + (size_t)min(bi*128 + ar, N5-1)*N5;

    float4 aR[4], bR[BCNT];

    auto loadRegs = [&](int c){
        const int k0 = kbase + c*32;
#pragma unroll
        for (int j = 0; j < 4; j++) aR[j] = *(const float4*)&aptr[k0 + aseg*16 + j*4];
#pragma unroll
        for (int i = 0; i < BCNT; i++){
            int idx = t + i*256;
            int br = idx/NB4, bc = idx%NB4;
            int gk = k0 + br;
            bR[i] = (gk < kend) ? *(const float4*)&Pk[(size_t)gk*BN + bc*4]
                                : make_float4(0,0,0,0);
        }
    };
    auto storeTiles = [&](int s){
        unsigned* As = Asm + s*ASZ;
        unsigned* Bs = Bsm + s*BSZ;
#pragma unroll
        for (int j = 0; j < 4; j++){
            int col = aseg*16 + j*4;
            As[(col+0)*136 + ar] = uf(aR[j].x);
            As[(col+1)*136 + ar] = uf(aR[j].y);
            As[(col+2)*136 + ar] = uf(aR[j].z);
            As[(col+3)*136 + ar] = uf(aR[j].w);
        }
#pragma unroll
        for (int i = 0; i < BCNT; i++){
            int idx = t + i*256;
            int br = idx/NB4, bc = idx%NB4;
            *(uint4*)&Bs[br*BP + bc*4] = *(uint4*)&bR[i];
        }
    };

    float acc[2][NT][4];
#pragma unroll
    for (int mt = 0; mt < 2; mt++)
#pragma unroll
        for (int nt = 0; nt < NT; nt++)
#pragma unroll
            for (int q = 0; q < 4; q++) acc[mt][nt][q] = 0.f;

    loadRegs(0);
    storeTiles(0);
    if (nch > 1) loadRegs(1);
    __syncthreads();

    for (int c = 0; c < nch; c++){
        const int s = c & 1;
        if (c+1 < nch) storeTiles(s^1);       // regs hold chunk c+1
        if (c+2 < nch) loadRegs(c+2);         // overlap global with MMA
        const unsigned* As = Asm + s*ASZ;
        const unsigned* Bs = Bsm + s*BSZ;
#pragma unroll
        for (int kk = 0; kk < 4; kk++){
            const int k = kk*8;
            unsigned a[2][4];
#pragma unroll
            for (int mt = 0; mt < 2; mt++){
                int m0 = wm*32 + mt*16;
                a[mt][0]=As[(k+ctg)*136 + m0+g];   a[mt][1]=As[(k+ctg)*136 + m0+g+8];
                a[mt][2]=As[(k+ctg+4)*136 + m0+g]; a[mt][3]=As[(k+ctg+4)*136 + m0+g+8];
            }
#pragma unroll
            for (int nt = 0; nt < NT; nt++){
                int n = wn*(BN/2) + nt*8 + g;
                unsigned b0 = Bs[(k+ctg)*BP + n], b1 = Bs[(k+ctg+4)*BP + n];
                mma8(acc[0][nt], a[0], b0, b1);
                mma8(acc[1][nt], a[1], b0, b1);
            }
        }
        __syncthreads();
    }

    float* dst = g_part + (size_t)y*N5*BN;
#pragma unroll
    for (int mt = 0; mt < 2; mt++){
#pragma unroll
        for (int nt = 0; nt < NT; nt++){
            int i0 = bi*128 + wm*32 + mt*16 + g;
            int n  = wn*(BN/2) + nt*8 + ctg*2;
            if (i0 < N5)
                *(float2*)&dst[(size_t)i0*BN + n] =
                    make_float2(acc[mt][nt][0], acc[mt][nt][1]);
            if (i0+8 < N5)
                *(float2*)&dst[(size_t)(i0+8)*BN + n] =
                    make_float2(acc[mt][nt][2], acc[mt][nt][3]);
        }
    }
}

// ---------------- fused: g_base = elu(g_acc + 16 partials), col min/max partials ------
template<int C>
__global__ void k_winred_mm()
{
    __shared__ float smn[4][128], smx[4][128];
    const int t = threadIdx.x;
    const int c = t % C, rp = t / C;
    const int r0 = blockIdx.x*25;
    float mn = 3.4e38f, mx = -3.4e38f;
    for (int r = rp; r < 25; r += 4){
        size_t idx = (size_t)(r0 + r)*C + c;
        float v = g_acc[idx];
#pragma unroll
        for (int s = 0; s < 16; s++) v += g_part[(size_t)s*N5*C + idx];
        v = eluf(v);
        g_base[idx] = v;
        mn = fminf(mn, v); mx = fmaxf(mx, v);
    }
    smn[rp][c] = mn; smx[rp][c] = mx;
    __syncthreads();
    if (rp == 0){
        mn = fminf(fminf(smn[0][c], smn[1][c]), fminf(smn[2][c], smn[3][c]));
        mx = fmaxf(fmaxf(smx[0][c], smx[1][c]), fmaxf(smx[2][c], smx[3][c]));
        g_mnp[blockIdx.x*128 + c] = mn;
        g_mxp[blockIdx.x*128 + c] = mx;
    }
}

// ---------------- logits = des @ fc2_w + fc2_b (B rounded inline at load) ----------------
__global__ __launch_bounds__(256,2) void k_linear_tc(const float* __restrict__ B,
                                                     const float* __restrict__ bias,
                                                     float* __restrict__ out)
{
    __shared__ unsigned As[32][136];
    __shared__ __align__(16) unsigned Bs[32][136];

    const int t = threadIdx.x;
    const int w = t >> 5, lane = t & 31, g = lane >> 2, ctg = lane & 3;
    const int wm = w >> 1, wn = w & 1;
    const int bi = blockIdx.y, bj = blockIdx.x;
    const int ar = t >> 1, aseg = t & 1;
    const float* aptr = g_desr + (size_t)min(bi*128 + ar, N5-1)*256;

    float acc[2][8][4];
#pragma unroll
    for (int mt = 0; mt < 2; mt++)
#pragma unroll
        for (int nt = 0; nt < 8; nt++)
#pragma unroll
            for (int q = 0; q < 4; q++) acc[mt][nt][q] = 0.f;

    for (int c = 0; c < 8; c++){
        const int k0 = c*32;
        __syncthreads();
#pragma unroll
        for (int j = 0; j < 4; j++){
            int col = aseg*16 + j*4;
            float4 v = *(const float4*)&aptr[k0 + col];
            As[col+0][ar] = uf(v.x);
            As[col+1][ar] = uf(v.y);
            As[col+2][ar] = uf(v.z);
            As[col+3][ar] = uf(v.w);
        }
#pragma unroll
        for (int i = 0; i < 4; i++){
            int idx = t + i*256;
            int br = idx >> 5, bc = idx & 31;
            int gj = bj*128 + bc*4;
            float4 v;
            if (gj + 3 < N5) v = *(const float4*)&B[(size_t)(k0+br)*N5 + gj];
            else {
                v = make_float4(0,0,0,0);
                if (gj+0 < N5) v.x = B[(size_t)(k0+br)*N5 + gj+0];
                if (gj+1 < N5) v.y = B[(size_t)(k0+br)*N5 + gj+1];
                if (gj+2 < N5) v.z = B[(size_t)(k0+br)*N5 + gj+2];
                if (gj+3 < N5) v.w = B[(size_t)(k0+br)*N5 + gj+3];
            }
            *(uint4*)&Bs[br][bc*4] = make_uint4(tf32r(v.x), tf32r(v.y), tf32r(v.z), tf32r(v.w));
        }
        __syncthreads();
#pragma unroll
        for (int kk = 0; kk < 4; kk++){
            const int k = kk*8;
            unsigned a[2][4];
#pragma unroll
            for (int mt = 0; mt < 2; mt++){
                int m0 = wm*32 + mt*16;
                a[mt][0]=As[k+ctg][m0+g];   a[mt][1]=As[k+ctg][m0+g+8];
                a[mt][2]=As[k+ctg+4][m0+g]; a[mt][3]=As[k+ctg+4][m0+g+8];
            }
#pragma unroll
            for (int nt = 0; nt < 8; nt++){
                int n = wn*64 + nt*8 + g;
                unsigned b0 = Bs[k+ctg][n], b1 = Bs[k+ctg+4][n];
                mma8(acc[0][nt], a[0], b0, b1);
                mma8(acc[1][nt], a[1], b0, b1);
            }
        }
    }
#pragma unroll
    for (int mt = 0; mt < 2; mt++){
#pragma unroll
        for (int nt = 0; nt < 8; nt++){
            int i0 = bi*128 + wm*32 + mt*16 + g;
            int jb = bj*128 + wn*64 + nt*8 + ctg*2;
            float b0 = (jb   < N5) ? bias[jb]   : 0.f;
            float b1 = (jb+1 < N5) ? bias[jb+1] : 0.f;
            if (i0 < N5 && jb < N5){
                if (jb+1 < N5)
                    *(float2*)&out[(size_t)i0*N5 + jb] =
                        make_float2(acc[mt][nt][0]+b0, acc[mt][nt][1]+b1);
                else out[(size_t)i0*N5 + jb] = acc[mt][nt][0]+b0;
            }
            if (i0+8 < N5 && jb < N5){
                if (jb+1 < N5)
                    *(float2*)&out[(size_t)(i0+8)*N5 + jb] =
                        make_float2(acc[mt][nt][2]+b0, acc[mt][nt][3]+b1);
                else out[(size_t)(i0+8)*N5 + jb] = acc[mt][nt][2]+b0;
            }
        }
    }
}

// ---------------- log-softmax, register-resident ----------------
__global__ void k_logsoftmax(float* __restrict__ out)
{
    const int row = blockIdx.x;
    float* p = out + (size_t)row*N5;
    const int t = threadIdx.x;
    float4 v[5];
    bool have[5];
    float mx = -3.4e38f;
#pragma unroll
    for (int s = 0; s < 5; s++){
        int i4 = t + s*256;
        have[s] = i4 < 1250;
        if (have[s]){
            v[s] = *(const float4*)&p[i4*4];
            mx = fmaxf(mx, fmaxf(fmaxf(v[s].x, v[s].y), fmaxf(v[s].z, v[s].w)));
        }
    }
    __shared__ float sh[256];
    sh[t] = mx; __syncthreads();
    for (int s = 128; s > 0; s >>= 1){
        if (t < s) sh[t] = fmaxf(sh[t], sh[t+s]);
        __syncthreads();
    }
    mx = sh[0]; __syncthreads();
    float sum = 0.f;
#pragma unroll
    for (int s = 0; s < 5; s++)
        if (have[s])
            sum += expf(v[s].x-mx) + expf(v[s].y-mx) + expf(v[s].z-mx) + expf(v[s].w-mx);
    sh[t] = sum; __syncthreads();
    for (int s = 128; s > 0; s >>= 1){
        if (t < s) sh[t] += sh[t+s];
        __syncthreads();
    }
    float lse = mx + logf(sh[0]);
#pragma unroll
    for (int s = 0; s < 5; s++){
        if (have[s]){
            int i4 = t + s*256;
            *(float4*)&p[i4*4] = make_float4(v[s].x-lse, v[s].y-lse, v[s].z-lse, v[s].w-lse);
        }
    }
}

// ---------------- launcher ----------------
extern "C" void kernel_launch(void* const* d_in, const int* in_sizes, int n_in,
                              void* d_out, int out_size)
{
    (void)in_sizes; (void)n_in;
    const float* x    = (const float*)d_in[0];
    const float* V    = (const float*)d_in[1];
    const float* A    = (const float*)d_in[2];
    const float* clk  = (const float*)d_in[3];
    const float* Wc[6] = {(const float*)d_in[4], (const float*)d_in[5],
                          (const float*)d_in[6], (const float*)d_in[7],
                          (const float*)d_in[8], (const float*)d_in[9]};
    const float* fc1w = (const float*)d_in[10];
    const float* fc1b = (const float*)d_in[11];
    const float* fc2w = (const float*)d_in[12];
    const float* fc2b = (const float*)d_in[13];
    float* out = (float*)d_out;

    const int smWin96  = (2*32*136 + 2*32*104)*4;   // 61440
    const int smWin128 = (2*32*136 + 2*32*136)*4;   // 69632
    cudaFuncSetAttribute(k_winapply_tc<96>,  cudaFuncAttributeMaxDynamicSharedMemorySize, smWin96);
    cudaFuncSetAttribute(k_winapply_tc<128>, cudaFuncAttributeMaxDynamicSharedMemorySize, smWin128);

    // preamble
    k_clkz<<<1,256>>>(clk);
    k_mm_part<<<200,512>>>(x, 128);
    k_colfin<<<1,128>>>(128);

    // Build Win (tf32-rounded M^2, symmetric tiles) + column norms -> icol2
    k_build_sym<<<dim3(820,4),256>>>(A, V);
    k_colreduce<<<dim3(20,4),256>>>();

    // Layer 1: 128 -> 96  (proj normalizes x inline)
    k_proj_tc<128,96><<<dim3(40,5),256>>>(Wc[0], x);
    k_winapply_tc<96><<<dim3(40,16),256,smWin96>>>();
    k_winred_mm<96><<<200,384>>>();
    k_colfin<<<1,128>>>(96);

    // Layers 2-5: 96 -> 96
    for (int L = 1; L < 5; L++){
        k_proj_tc<96,96><<<dim3(40,5),256>>>(Wc[L], nullptr);
        k_winapply_tc<96><<<dim3(40,16),256,smWin96>>>();
        k_winred_mm<96><<<200,384>>>();
        k_colfin<<<1,128>>>(96);
    }

    // Layer 6: 96 -> 128
    k_proj_tc<96,128><<<dim3(40,5),256>>>(Wc[5], nullptr);
    k_winapply_tc<128><<<dim3(40,16),256,smWin128>>>();
    k_winred_mm<128><<<200,512>>>();
    k_colfin<<<1,128>>>(128);

    // des = elu(fmaxmin(h) @ fc1_w + fc1_b) -> g_desr (rounded) + out region (exact)
    float* desout = (out_size >= 25000000 + N5*256) ? (out + 25000000) : nullptr;
    k_proj_des<128,256><<<79,256>>>(fc1w, fc1b, desout);

    // logits + log_softmax
    k_linear_tc<<<dim3(40,40),256>>>(fc2w, fc2b, out);
    k_logsoftmax<<<5000,256>>>(out);
}